// round 3
// baseline (speedup 1.0000x reference)
#include <cuda_runtime.h>
#include <cuda_bf16.h>

// Problem dims
#define BB 1024
#define CC 80
#define DW 300
#define JJ 8000
#define ICH 2048

// Scratch (device globals; no allocations allowed)
__device__ float g_adj[CC * CC];
__device__ float g_P[CC * DW];          // adj @ inp0
__device__ float g_x1[CC * 1024];       // leaky((adj@inp0) @ W_gc1)
__device__ float g_Q[CC * 1024];        // adj @ x1
__device__ float g_x2[CC * 2048];       // (adj@x1) @ W_gc2
__device__ float g_cls[CC * JJ];        // x2 @ W_cls^T + b_cls
__device__ float g_M[CC * 2048];        // cls @ W_img
__device__ float g_t[CC];               // cls @ b_img

// ---------------------------------------------------------------------------
// adj[i][j] = D[i] * A[j][i] * D[j],  D = rowsum(A)^-0.5
__global__ void adj_kernel(const float* __restrict__ A, float* __restrict__ adj) {
    __shared__ float D[CC];
    int tid = threadIdx.x;
    if (tid < CC) {
        float s = 0.f;
        #pragma unroll 4
        for (int j = 0; j < CC; j++) s += A[tid * CC + j];
        D[tid] = 1.0f / sqrtf(s);
    }
    __syncthreads();
    for (int idx = tid; idx < CC * CC; idx += blockDim.x) {
        int i = idx / CC, j = idx % CC;
        adj[idx] = D[i] * A[j * CC + i] * D[j];
    }
}

__global__ void zero_kernel(float* __restrict__ p, int n) {
    int i = blockIdx.x * blockDim.x + threadIdx.x;
    if (i < n) p[i] = 0.f;
}

// t[c] = sum_j cls[c,j] * b[j]
__global__ void dot_bias_kernel(const float* __restrict__ cls,
                                const float* __restrict__ b,
                                float* __restrict__ t, int J) {
    int c = blockIdx.x;
    float s = 0.f;
    for (int j = threadIdx.x; j < J; j += blockDim.x)
        s += cls[c * J + j] * b[j];
    #pragma unroll
    for (int o = 16; o > 0; o >>= 1) s += __shfl_down_sync(0xFFFFFFFFu, s, o);
    __shared__ float red[8];
    if ((threadIdx.x & 31) == 0) red[threadIdx.x >> 5] = s;
    __syncthreads();
    if (threadIdx.x == 0) {
        float tot = 0.f;
        #pragma unroll
        for (int w = 0; w < 8; w++) tot += red[w];
        t[c] = tot;
    }
}

// ---------------------------------------------------------------------------
// Generic tiled fp32 GEMM.
//   C[M,N] (+)= A[M,K] * op(B)            op(B) = B[K,N] (TB=false) or B[N,K] (TB=true)
// 256 threads = 16x16; each thread computes TM x TN outputs. BM = 16*TM, BN = 16*TN.
// gridDim.z > 1 => split-K with atomicAdd into pre-zeroed C.
// bias (over N) added once (z==0). leaky applied only when gridDim.z==1.
template<int BM, int BN, int BK, int TM, int TN, bool TB>
__global__ void __launch_bounds__(256)
sgemm(const float* __restrict__ A, const float* __restrict__ B,
      float* __restrict__ C, const float* __restrict__ bias,
      int M, int N, int K, int lda, int ldb, int ldc, int leaky) {
    __shared__ float As[BK][BM + 4];
    __shared__ float Bs[BK][BN + 4];

    const int tid = threadIdx.x;
    const int tr = tid >> 4;        // 0..15
    const int tc = tid & 15;        // 0..15
    const int m0 = blockIdx.x * BM;
    const int n0 = blockIdx.y * BN;

    int k_begin = 0, k_end = K;
    const bool split = (gridDim.z > 1);
    if (split) {
        int chunk = (K + gridDim.z - 1) / (int)gridDim.z;
        k_begin = blockIdx.z * chunk;
        k_end = min(K, k_begin + chunk);
    }

    float acc[TM][TN];
    #pragma unroll
    for (int i = 0; i < TM; i++)
        #pragma unroll
        for (int j = 0; j < TN; j++) acc[i][j] = 0.f;

    for (int k0 = k_begin; k0 < k_end; k0 += BK) {
        // Load A tile [BM x BK], store transposed As[k][m]
        #pragma unroll
        for (int idx = tid; idx < BM * BK; idx += 256) {
            int m = idx / BK, k = idx % BK;
            int gm = m0 + m, gk = k0 + k;
            float v = 0.f;
            if (gm < M && gk < k_end) v = A[gm * lda + gk];
            As[k][m] = v;
        }
        // Load B tile into Bs[k][n]
        #pragma unroll
        for (int idx = tid; idx < BN * BK; idx += 256) {
            if (TB) {
                int n = idx / BK, k = idx % BK;
                int gn = n0 + n, gk = k0 + k;
                float v = 0.f;
                if (gn < N && gk < k_end) v = B[gn * ldb + gk];
                Bs[k][n] = v;
            } else {
                int k = idx / BN, n = idx % BN;
                int gn = n0 + n, gk = k0 + k;
                float v = 0.f;
                if (gn < N && gk < k_end) v = B[gk * ldb + gn];
                Bs[k][n] = v;
            }
        }
        __syncthreads();

        #pragma unroll
        for (int k = 0; k < BK; k++) {
            float a[TM], b[TN];
            #pragma unroll
            for (int i = 0; i < TM; i++) a[i] = As[k][tr * TM + i];
            #pragma unroll
            for (int j = 0; j < TN; j++) b[j] = Bs[k][tc * TN + j];
            #pragma unroll
            for (int i = 0; i < TM; i++)
                #pragma unroll
                for (int j = 0; j < TN; j++) acc[i][j] = fmaf(a[i], b[j], acc[i][j]);
        }
        __syncthreads();
    }

    const bool add_bias = (bias != nullptr) && (!split || blockIdx.z == 0);
    #pragma unroll
    for (int i = 0; i < TM; i++) {
        int gm = m0 + tr * TM + i;
        if (gm >= M) continue;
        #pragma unroll
        for (int j = 0; j < TN; j++) {
            int gn = n0 + tc * TN + j;
            if (gn >= N) continue;
            float v = acc[i][j];
            if (add_bias) v += bias[gn];
            if (leaky) v = (v > 0.f) ? v : 0.2f * v;
            if (split) atomicAdd(&C[gm * ldc + gn], v);
            else C[gm * ldc + gn] = v;
        }
    }
}

// ---------------------------------------------------------------------------
extern "C" void kernel_launch(void* const* d_in, const int* in_sizes, int n_in,
                              void* d_out, int out_size) {
    const float* feature = (const float*)d_in[0];   // [1024, 2048]
    const float* inp     = (const float*)d_in[1];   // [1, 80, 300]
    const float* A       = (const float*)d_in[2];   // [80, 80]
    const float* Wgc1    = (const float*)d_in[3];   // [300, 1024]
    const float* Wgc2    = (const float*)d_in[4];   // [1024, 2048]
    const float* Wimg    = (const float*)d_in[5];   // [8000, 2048]
    const float* bimg    = (const float*)d_in[6];   // [8000]
    const float* Wcls    = (const float*)d_in[7];   // [8000, 2048]
    const float* bcls    = (const float*)d_in[8];   // [8000]
    float* out = (float*)d_out;                     // [1024, 80]

    float *adj, *P, *x1, *Q, *x2, *cls, *Mm, *t;
    cudaGetSymbolAddress((void**)&adj, g_adj);
    cudaGetSymbolAddress((void**)&P,   g_P);
    cudaGetSymbolAddress((void**)&x1,  g_x1);
    cudaGetSymbolAddress((void**)&Q,   g_Q);
    cudaGetSymbolAddress((void**)&x2,  g_x2);
    cudaGetSymbolAddress((void**)&cls, g_cls);
    cudaGetSymbolAddress((void**)&Mm,  g_M);
    cudaGetSymbolAddress((void**)&t,   g_t);

    // Zero split-K accumulation targets
    zero_kernel<<<(CC * 2048 + 255) / 256, 256>>>(x2, CC * 2048);
    zero_kernel<<<(CC * JJ + 255) / 256, 256>>>(cls, CC * JJ);
    zero_kernel<<<(CC * 2048 + 255) / 256, 256>>>(Mm, CC * 2048);
    zero_kernel<<<(BB * CC + 255) / 256, 256>>>(out, BB * CC);

    // adj (tiny)
    adj_kernel<<<1, 256>>>(A, adj);

    // P = adj @ inp0                      [80,300] K=80
    sgemm<80, 64, 16, 5, 4, false><<<dim3(1, 5, 1), 256>>>(
        adj, inp, P, nullptr, CC, DW, CC, CC, DW, DW, 0);

    // x1 = leaky(P @ W_gc1)               [80,1024] K=300
    sgemm<80, 64, 16, 5, 4, false><<<dim3(1, 16, 1), 256>>>(
        P, Wgc1, x1, nullptr, CC, 1024, DW, DW, 1024, 1024, 1);

    // Q = adj @ x1                        [80,1024] K=80
    sgemm<80, 64, 16, 5, 4, false><<<dim3(1, 16, 1), 256>>>(
        adj, x1, Q, nullptr, CC, 1024, CC, CC, 1024, 1024, 0);

    // x2 = Q @ W_gc2                      [80,2048] K=1024, split-K 4
    sgemm<80, 64, 16, 5, 4, false><<<dim3(1, 32, 4), 256>>>(
        Q, Wgc2, x2, nullptr, CC, 2048, 1024, 1024, 2048, 2048, 0);

    // cls = x2 @ W_cls^T + b_cls          [80,8000] K=2048, split-K 4
    sgemm<80, 64, 16, 5, 4, true><<<dim3(1, 125, 4), 256>>>(
        x2, Wcls, cls, bcls, CC, JJ, 2048, 2048, 2048, JJ, 0);

    // t = cls @ b_img                     [80]
    dot_bias_kernel<<<CC, 256>>>(cls, bimg, t, JJ);

    // M = cls @ W_img                     [80,2048] K=8000, split-K 8
    sgemm<80, 64, 16, 5, 4, false><<<dim3(1, 32, 8), 256>>>(
        cls, Wimg, Mm, nullptr, CC, 2048, JJ, JJ, 2048, 2048, 0);

    // out = feature @ M^T + t             [1024,80] K=2048, split-K 8
    sgemm<64, 80, 16, 4, 5, true><<<dim3(16, 1, 8), 256>>>(
        feature, Mm, out, t, BB, CC, 2048, 2048, 2048, CC, 0);
}

// round 4
// speedup vs baseline: 1.1608x; 1.1608x over previous
#include <cuda_runtime.h>
#include <cuda_bf16.h>

// Problem dims
#define BB 1024
#define CC 80
#define DW 300
#define JJ 8000
#define ICH 2048

// ---- scratch layout in one device global (no allocations allowed) ----------
#define OFF_ADJ 0
#define SZ_ADJ  (CC*CC)              // 6400
#define OFF_P   (OFF_ADJ + SZ_ADJ)
#define SZ_P    (CC*DW)              // 24000
#define OFF_Q   (OFF_P + SZ_P)
#define SZ_Q    (CC*1024)            // 81920
#define OFF_T   (OFF_Q + SZ_Q)
#define SZ_T    (CC)
// zeroed region (split-K atomic targets) must be contiguous:
#define OFF_X1  (OFF_T + SZ_T)
#define SZ_X1   (CC*1024)
#define OFF_X2  (OFF_X1 + SZ_X1)
#define SZ_X2   (CC*2048)
#define OFF_CLS (OFF_X2 + SZ_X2)
#define SZ_CLS  (CC*JJ)
#define OFF_M   (OFF_CLS + SZ_CLS)
#define SZ_M    (CC*2048)
#define SZ_ZERO (SZ_X1 + SZ_X2 + SZ_CLS + SZ_M)
#define SZ_TOT  (OFF_M + SZ_M)

__device__ float g_buf[SZ_TOT];

// ---------------------------------------------------------------------------
__global__ void adj_kernel(const float* __restrict__ A, float* __restrict__ adj) {
    __shared__ float D[CC];
    int tid = threadIdx.x;
    if (tid < CC) {
        float s = 0.f;
        #pragma unroll 4
        for (int j = 0; j < CC; j++) s += A[tid * CC + j];
        D[tid] = 1.0f / sqrtf(s);
    }
    __syncthreads();
    for (int idx = tid; idx < CC * CC; idx += blockDim.x) {
        int i = idx / CC, j = idx % CC;
        adj[idx] = D[i] * A[j * CC + i] * D[j];
    }
}

// Zero the split-K accumulation region + out in one launch.
__global__ void zero2_kernel(float* __restrict__ a, int na,
                             float* __restrict__ b, int nb) {
    int i = blockIdx.x * blockDim.x + threadIdx.x;
    if (i < na) a[i] = 0.f;
    else if (i - na < nb) b[i - na] = 0.f;
}

// t[c] = sum_j cls[c,j] * b[j]
__global__ void dot_bias_kernel(const float* __restrict__ cls,
                                const float* __restrict__ b,
                                float* __restrict__ t, int J) {
    int c = blockIdx.x;
    float s = 0.f;
    for (int j = threadIdx.x; j < J; j += blockDim.x)
        s += cls[c * J + j] * b[j];
    #pragma unroll
    for (int o = 16; o > 0; o >>= 1) s += __shfl_down_sync(0xFFFFFFFFu, s, o);
    __shared__ float red[8];
    if ((threadIdx.x & 31) == 0) red[threadIdx.x >> 5] = s;
    __syncthreads();
    if (threadIdx.x == 0) {
        float tot = 0.f;
        #pragma unroll
        for (int w = 0; w < 8; w++) tot += red[w];
        t[c] = tot;
    }
}

// ---------------------------------------------------------------------------
// M=80 GEMM with packed fp32x2 FMA (Blackwell FFMA2 path, PTX-only).
//   C[80,N] (+)= A[80,K] * op(B), op(B)=B[K,N] (TB=false) or B[N,K] (TB=true)
// 256 threads = 8 x 32. Each thread: 10 rows (5 packed pairs via LDS.64) x 4 cols
// (one LDS.128) -> 20 fma.rn.f32x2 = 40 MACs per k.
// gridDim.z>1 => split-K, atomicAdd into pre-zeroed C.
// leaky_b: apply leaky-relu(0.2) to B elements at load (TB=false path).
// transC: store C[n*ldc + m] instead of C[m*ldc + n].
template<bool TB>
__global__ void __launch_bounds__(256)
gemm80(const float* __restrict__ A, const float* __restrict__ B,
       float* __restrict__ C, const float* __restrict__ bias_n,
       const float* __restrict__ bias_m,
       int N, int K, int lda, int ldb, int ldc, int leaky_b, int transC) {
    __shared__ float As[16][80];     // [k][m], rows 320B (8B-aligned pairs)
    __shared__ float Bs[16][128];    // [k][n], rows 512B (16B-aligned quads)

    const int tid = threadIdx.x;
    const int tr = tid >> 5;         // 0..7   -> m base = tr*10
    const int tc = tid & 31;         // 0..31  -> n base = tc*4
    const int n0 = blockIdx.y * 128;

    const int chunk = (K + gridDim.z - 1) / (int)gridDim.z;
    const int kb = blockIdx.z * chunk;
    const int ke = min(K, kb + chunk);

    unsigned long long acc[5][4];
    #pragma unroll
    for (int i = 0; i < 5; i++)
        #pragma unroll
        for (int j = 0; j < 4; j++) acc[i][j] = 0ULL;

    for (int k0 = kb; k0 < ke; k0 += 16) {
        // ---- load A tile [80 x 16] transposed into As[k][m] (scalar, coalesced)
        #pragma unroll
        for (int t = 0; t < 5; t++) {
            int idx = tid + t * 256;
            int m = idx >> 4, k = idx & 15;
            int gk = k0 + k;
            As[k][m] = (gk < ke) ? A[(size_t)m * lda + gk] : 0.f;
        }
        // ---- load B tile into Bs[k][n]
        if (TB) {
            // B is [N, K] row-major: contiguous along k -> vec4 + transpose store
            #pragma unroll
            for (int t = 0; t < 2; t++) {
                int idx = tid + t * 256;
                int n  = idx >> 2;
                int kq = (idx & 3) << 2;
                int gn = n0 + n;
                float4 v = make_float4(0.f, 0.f, 0.f, 0.f);
                if (gn < N) {
                    if (k0 + kq + 4 <= ke) {
                        v = *(const float4*)(B + (size_t)gn * ldb + k0 + kq);
                    } else {
                        float tmp[4] = {0.f, 0.f, 0.f, 0.f};
                        #pragma unroll
                        for (int p = 0; p < 4; p++)
                            if (k0 + kq + p < ke)
                                tmp[p] = B[(size_t)gn * ldb + k0 + kq + p];
                        v = make_float4(tmp[0], tmp[1], tmp[2], tmp[3]);
                    }
                }
                Bs[kq + 0][n] = v.x;
                Bs[kq + 1][n] = v.y;
                Bs[kq + 2][n] = v.z;
                Bs[kq + 3][n] = v.w;
            }
        } else {
            // B is [K, N] row-major: contiguous along n -> vec4 direct
            #pragma unroll
            for (int t = 0; t < 2; t++) {
                int idx = tid + t * 256;
                int k  = idx >> 5;
                int nv = (idx & 31) << 2;
                int gk = k0 + k;
                int gn = n0 + nv;
                float4 v = make_float4(0.f, 0.f, 0.f, 0.f);
                if (gk < ke) {
                    if (gn + 4 <= N) {
                        v = *(const float4*)(B + (size_t)gk * ldb + gn);
                    } else {
                        float tmp[4] = {0.f, 0.f, 0.f, 0.f};
                        #pragma unroll
                        for (int p = 0; p < 4; p++)
                            if (gn + p < N) tmp[p] = B[(size_t)gk * ldb + gn + p];
                        v = make_float4(tmp[0], tmp[1], tmp[2], tmp[3]);
                    }
                }
                if (leaky_b) {
                    v.x = v.x > 0.f ? v.x : 0.2f * v.x;
                    v.y = v.y > 0.f ? v.y : 0.2f * v.y;
                    v.z = v.z > 0.f ? v.z : 0.2f * v.z;
                    v.w = v.w > 0.f ? v.w : 0.2f * v.w;
                }
                *(float4*)&Bs[k][nv] = v;
            }
        }
        __syncthreads();

        // ---- compute: 16 k-steps x 20 fma.rn.f32x2
        #pragma unroll
        for (int k = 0; k < 16; k++) {
            unsigned long long a2[5];
            const unsigned long long* ap =
                (const unsigned long long*)&As[k][tr * 10];
            #pragma unroll
            for (int i = 0; i < 5; i++) a2[i] = ap[i];   // (m, m+1) packed

            float4 bv = *(const float4*)&Bs[k][tc * 4];
            unsigned long long b2[4];
            asm("mov.b64 %0, {%1, %1};" : "=l"(b2[0]) : "r"(__float_as_uint(bv.x)));
            asm("mov.b64 %0, {%1, %1};" : "=l"(b2[1]) : "r"(__float_as_uint(bv.y)));
            asm("mov.b64 %0, {%1, %1};" : "=l"(b2[2]) : "r"(__float_as_uint(bv.z)));
            asm("mov.b64 %0, {%1, %1};" : "=l"(b2[3]) : "r"(__float_as_uint(bv.w)));

            #pragma unroll
            for (int i = 0; i < 5; i++)
                #pragma unroll
                for (int j = 0; j < 4; j++)
                    asm("fma.rn.f32x2 %0, %1, %2, %0;"
                        : "+l"(acc[i][j]) : "l"(a2[i]), "l"(b2[j]));
        }
        __syncthreads();
    }

    // ---- epilogue
    const bool split = (gridDim.z > 1);
    const bool first = (blockIdx.z == 0);
    #pragma unroll
    for (int i = 0; i < 5; i++) {
        #pragma unroll
        for (int j = 0; j < 4; j++) {
            int gn = n0 + tc * 4 + j;
            if (gn >= N) continue;
            unsigned int ulo, uhi;
            asm("mov.b64 {%0, %1}, %2;" : "=r"(ulo), "=r"(uhi) : "l"(acc[i][j]));
            float vals[2] = {__uint_as_float(ulo), __uint_as_float(uhi)};
            #pragma unroll
            for (int p = 0; p < 2; p++) {
                int gm = tr * 10 + 2 * i + p;
                float v = vals[p];
                if (first) {
                    if (bias_n) v += bias_n[gn];
                    if (bias_m) v += bias_m[gm];
                }
                float* dst = transC ? (C + (size_t)gn * ldc + gm)
                                    : (C + (size_t)gm * ldc + gn);
                if (split) atomicAdd(dst, v);
                else *dst = v;
            }
        }
    }
}

// ---------------------------------------------------------------------------
extern "C" void kernel_launch(void* const* d_in, const int* in_sizes, int n_in,
                              void* d_out, int out_size) {
    const float* feature = (const float*)d_in[0];   // [1024, 2048]
    const float* inp     = (const float*)d_in[1];   // [1, 80, 300]
    const float* A       = (const float*)d_in[2];   // [80, 80]
    const float* Wgc1    = (const float*)d_in[3];   // [300, 1024]
    const float* Wgc2    = (const float*)d_in[4];   // [1024, 2048]
    const float* Wimg    = (const float*)d_in[5];   // [8000, 2048]
    const float* bimg    = (const float*)d_in[6];   // [8000]
    const float* Wcls    = (const float*)d_in[7];   // [8000, 2048]
    const float* bcls    = (const float*)d_in[8];   // [8000]
    float* out = (float*)d_out;                     // [1024, 80] row-major

    float* buf;
    cudaGetSymbolAddress((void**)&buf, g_buf);
    float* adj = buf + OFF_ADJ;
    float* P   = buf + OFF_P;
    float* Q   = buf + OFF_Q;
    float* t   = buf + OFF_T;
    float* x1  = buf + OFF_X1;
    float* x2  = buf + OFF_X2;
    float* cls = buf + OFF_CLS;
    float* Mm  = buf + OFF_M;

    // Zero split-K targets (x1,x2,cls,Mm contiguous) + out, one launch.
    {
        int ntot = SZ_ZERO + BB * CC;
        zero2_kernel<<<(ntot + 255) / 256, 256>>>(x1, SZ_ZERO, out, BB * CC);
    }

    adj_kernel<<<1, 256>>>(A, adj);

    // P = adj @ inp0                       [80,300]  K=80
    gemm80<false><<<dim3(1, 3, 1), 256>>>(
        adj, inp, P, nullptr, nullptr, DW, CC, CC, DW, DW, 0, 0);

    // x1 = P @ W_gc1 (pre-activation)      [80,1024] K=300, split 2
    gemm80<false><<<dim3(1, 8, 2), 256>>>(
        P, Wgc1, x1, nullptr, nullptr, 1024, DW, DW, 1024, 1024, 0, 0);

    // Q = adj @ leaky(x1)                  [80,1024] K=80 (leaky fused into B load)
    gemm80<false><<<dim3(1, 8, 1), 256>>>(
        adj, x1, Q, nullptr, nullptr, 1024, CC, CC, 1024, 1024, 1, 0);

    // x2 = Q @ W_gc2                       [80,2048] K=1024, split 8
    gemm80<false><<<dim3(1, 16, 8), 256>>>(
        Q, Wgc2, x2, nullptr, nullptr, 2048, 1024, 1024, 2048, 2048, 0, 0);

    // cls = x2 @ W_cls^T + b_cls           [80,8000] K=2048, split 8
    gemm80<true><<<dim3(1, 63, 8), 256>>>(
        x2, Wcls, cls, bcls, nullptr, JJ, 2048, 2048, 2048, JJ, 0, 0);

    // t = cls @ b_img                      [80]
    dot_bias_kernel<<<CC, 256>>>(cls, bimg, t, JJ);

    // M = cls @ W_img                      [80,2048] K=8000, split 20
    gemm80<false><<<dim3(1, 16, 20), 256>>>(
        cls, Wimg, Mm, nullptr, nullptr, 2048, JJ, JJ, 2048, 2048, 0, 0);

    // out^T: C[c, b] = Mm[c,:] . feature[b,:] + t[c], stored to out[b*80 + c]
    //                                      [80,1024] K=2048, split 16
    gemm80<true><<<dim3(1, 8, 16), 256>>>(
        Mm, feature, out, nullptr, t, BB, 2048, 2048, 2048, CC, 0, 1);
}

// round 7
// speedup vs baseline: 1.4464x; 1.2460x over previous
#include <cuda_runtime.h>
#include <cuda_bf16.h>

// Problem dims
#define BB 1024
#define CC 80
#define DW 300
#define JJ 8000
#define ICH 2048

// ---- scratch layout in one device global (no allocations allowed) ----------
// Non-zeroed: adj, P, t. Zeroed (split-K atomic targets, contiguous): Q,x1,x2,cls,M
#define OFF_ADJ 0
#define SZ_ADJ  (CC*CC)
#define OFF_P   (OFF_ADJ + SZ_ADJ)
#define SZ_P    (CC*DW)
#define OFF_T   (OFF_P + SZ_P)
#define SZ_T    (CC)
#define OFF_Q   (OFF_T + SZ_T)
#define SZ_Q    (CC*1024)
#define OFF_X1  (OFF_Q + SZ_Q)
#define SZ_X1   (CC*1024)
#define OFF_X2  (OFF_X1 + SZ_X1)
#define SZ_X2   (CC*2048)
#define OFF_CLS (OFF_X2 + SZ_X2)
#define SZ_CLS  (CC*JJ)
#define OFF_M   (OFF_CLS + SZ_CLS)
#define SZ_M    (CC*2048)
#define SZ_ZERO (SZ_Q + SZ_X1 + SZ_X2 + SZ_CLS + SZ_M)
#define SZ_TOT  (OFF_M + SZ_M)

__device__ float g_buf[SZ_TOT];

// ---------------------------------------------------------------------------
__global__ void adj_kernel(const float* __restrict__ A, float* __restrict__ adj) {
    __shared__ float D[CC];
    int tid = threadIdx.x;
    if (tid < CC) {
        float s = 0.f;
        #pragma unroll 4
        for (int j = 0; j < CC; j++) s += A[tid * CC + j];
        D[tid] = 1.0f / sqrtf(s);
    }
    __syncthreads();
    for (int idx = tid; idx < CC * CC; idx += blockDim.x) {
        int i = idx / CC, j = idx % CC;
        adj[idx] = D[i] * A[j * CC + i] * D[j];
    }
}

// Zero the split-K accumulation region + out in one launch.
__global__ void zero2_kernel(float* __restrict__ a, int na,
                             float* __restrict__ b, int nb) {
    int i = blockIdx.x * blockDim.x + threadIdx.x;
    if (i < na) a[i] = 0.f;
    else if (i - na < nb) b[i - na] = 0.f;
}

// t[c] = sum_j cls[c,j] * b[j]
__global__ void dot_bias_kernel(const float* __restrict__ cls,
                                const float* __restrict__ b,
                                float* __restrict__ t, int J) {
    int c = blockIdx.x;
    float s = 0.f;
    for (int j = threadIdx.x; j < J; j += blockDim.x)
        s += cls[c * J + j] * b[j];
    #pragma unroll
    for (int o = 16; o > 0; o >>= 1) s += __shfl_down_sync(0xFFFFFFFFu, s, o);
    __shared__ float red[8];
    if ((threadIdx.x & 31) == 0) red[threadIdx.x >> 5] = s;
    __syncthreads();
    if (threadIdx.x == 0) {
        float tot = 0.f;
        #pragma unroll
        for (int w = 0; w < 8; w++) tot += red[w];
        t[c] = tot;
    }
}

// ---------------------------------------------------------------------------
// M=80 GEMM, packed fp32x2 FMA, double-buffered smem, duplicated-B layout.
//   C[80,N] (+)= A[80,K] * op(B), op(B)=B[K,N] (TB=false) or B[N,K] (TB=true)
// 256 threads = 8 x 32. Thread (tr,tc): rows tr*10..+9 (5 packed m-pairs),
// cols {tc, tc+32, tc+64, tc+96}. Bs holds {v,v} float2 -> FFMA2 b-operand is a
// direct conflict-free LDS.64; As m-pairs are warp-broadcast LDS.64.
// gridDim.z>1 => split-K, atomicAdd into pre-zeroed C.
template<bool TB>
__global__ void __launch_bounds__(256, 2)
gemm80(const float* __restrict__ A, const float* __restrict__ B,
       float* __restrict__ C, const float* __restrict__ bias_n,
       const float* __restrict__ bias_m,
       int N, int K, int lda, int ldb, int ldc, int leaky_b, int transC) {
    __shared__ float  As[2][16][82];    // [buf][k][m], row padded: conflict-free
    __shared__ float2 Bs[2][16][129];   // [buf][k][n] = {v,v}, row padded

    const int tid = threadIdx.x;
    const int tr = tid >> 5;            // 0..7 -> m base = tr*10
    const int tc = tid & 31;            // 0..31
    const int n0 = blockIdx.y * 128;

    const int chunk = (K + gridDim.z - 1) / (int)gridDim.z;
    const int kb = min(K, (int)blockIdx.z * chunk);
    const int ke = min(K, kb + chunk);
    const int ntiles = (ke - kb + 15) >> 4;

    // per-thread staging registers for the next tile
    float aR[5];
    float bR[8];

    // ---- tile load helpers (inlined by compiler) ----
    auto loadA = [&](int k0) {
        #pragma unroll
        for (int t = 0; t < 5; t++) {
            int idx = tid + t * 256;        // 80*16 = 1280 elems
            int m = idx >> 4, k = idx & 15;
            int gk = k0 + k;
            aR[t] = (gk < ke) ? A[(size_t)m * lda + gk] : 0.f;
        }
    };
    auto storeA = [&](int buf) {
        #pragma unroll
        for (int t = 0; t < 5; t++) {
            int idx = tid + t * 256;
            int m = idx >> 4, k = idx & 15;
            As[buf][k][m] = aR[t];
        }
    };
    auto loadB = [&](int k0) {
        if (TB) {
            // B[N,K]: lanes along k for coalescing
            #pragma unroll
            for (int t = 0; t < 8; t++) {
                int idx = tid + t * 256;    // 16k x 128n
                int k = idx & 15, n = idx >> 4;
                int gk = k0 + k, gn = n0 + n;
                float v = 0.f;
                if (gk < ke && gn < N) v = B[(size_t)gn * ldb + gk];
                bR[t] = v;
            }
        } else {
            // B[K,N]: lanes along n for coalescing
            #pragma unroll
            for (int t = 0; t < 8; t++) {
                int idx = tid + t * 256;
                int k = idx >> 7, n = idx & 127;
                int gk = k0 + k, gn = n0 + n;
                float v = 0.f;
                if (gk < ke && gn < N) v = B[(size_t)gk * ldb + gn];
                if (leaky_b) v = v > 0.f ? v : 0.2f * v;
                bR[t] = v;
            }
        }
    };
    auto storeB = [&](int buf) {
        #pragma unroll
        for (int t = 0; t < 8; t++) {
            int idx = tid + t * 256;
            int k, n;
            if (TB) { k = idx & 15; n = idx >> 4; }
            else    { k = idx >> 7; n = idx & 127; }
            Bs[buf][k][n] = make_float2(bR[t], bR[t]);
        }
    };

    unsigned long long acc[5][4];
    #pragma unroll
    for (int i = 0; i < 5; i++)
        #pragma unroll
        for (int j = 0; j < 4; j++) acc[i][j] = 0ULL;

    if (ntiles > 0) {
        loadA(kb); loadB(kb);
        storeA(0); storeB(0);
        __syncthreads();
    }

    for (int t = 0; t < ntiles; t++) {
        const int cur = t & 1;
        const bool more = (t + 1 < ntiles);
        if (more) { int k0n = kb + (t + 1) * 16; loadA(k0n); loadB(k0n); }

        #pragma unroll
        for (int k = 0; k < 16; k++) {
            unsigned long long a2[5], b2[4];
            const unsigned long long* ap =
                (const unsigned long long*)&As[cur][k][tr * 10];
            #pragma unroll
            for (int i = 0; i < 5; i++) a2[i] = ap[i];      // (m,m+1) pairs, broadcast
            #pragma unroll
            for (int j = 0; j < 4; j++)
                b2[j] = *(const unsigned long long*)&Bs[cur][k][tc + 32 * j];
            #pragma unroll
            for (int i = 0; i < 5; i++)
                #pragma unroll
                for (int j = 0; j < 4; j++)
                    asm("fma.rn.f32x2 %0, %1, %2, %0;"
                        : "+l"(acc[i][j]) : "l"(a2[i]), "l"(b2[j]));
        }

        if (more) { storeA(cur ^ 1); storeB(cur ^ 1); }
        __syncthreads();
    }

    // ---- epilogue
    const bool split = (gridDim.z > 1);
    const bool first = (blockIdx.z == 0);
    #pragma unroll
    for (int i = 0; i < 5; i++) {
        #pragma unroll
        for (int j = 0; j < 4; j++) {
            int gn = n0 + tc + 32 * j;
            if (gn >= N) continue;
            unsigned int ulo, uhi;
            asm("mov.b64 {%0, %1}, %2;" : "=r"(ulo), "=r"(uhi) : "l"(acc[i][j]));
            float vals[2] = {__uint_as_float(ulo), __uint_as_float(uhi)};
            #pragma unroll
            for (int p = 0; p < 2; p++) {
                int gm = tr * 10 + 2 * i + p;
                float v = vals[p];
                if (first) {
                    if (bias_n) v += bias_n[gn];
                    if (bias_m) v += bias_m[gm];
                }
                float* dst = transC ? (C + (size_t)gn * ldc + gm)
                                    : (C + (size_t)gm * ldc + gn);
                if (split) atomicAdd(dst, v);
                else *dst = v;
            }
        }
    }
}

// ---------------------------------------------------------------------------
extern "C" void kernel_launch(void* const* d_in, const int* in_sizes, int n_in,
                              void* d_out, int out_size) {
    const float* feature = (const float*)d_in[0];   // [1024, 2048]
    const float* inp     = (const float*)d_in[1];   // [1, 80, 300]
    const float* A       = (const float*)d_in[2];   // [80, 80]
    const float* Wgc1    = (const float*)d_in[3];   // [300, 1024]
    const float* Wgc2    = (const float*)d_in[4];   // [1024, 2048]
    const float* Wimg    = (const float*)d_in[5];   // [8000, 2048]
    const float* bimg    = (const float*)d_in[6];   // [8000]
    const float* Wcls    = (const float*)d_in[7];   // [8000, 2048]
    const float* bcls    = (const float*)d_in[8];   // [8000]
    float* out = (float*)d_out;                     // [1024, 80] row-major

    float* buf;
    cudaGetSymbolAddress((void**)&buf, g_buf);
    float* adj = buf + OFF_ADJ;
    float* P   = buf + OFF_P;
    float* t   = buf + OFF_T;
    float* Q   = buf + OFF_Q;
    float* x1  = buf + OFF_X1;
    float* x2  = buf + OFF_X2;
    float* cls = buf + OFF_CLS;
    float* Mm  = buf + OFF_M;

    // Zero split-K targets (Q,x1,x2,cls,Mm contiguous) + out, one launch.
    {
        int ntot = SZ_ZERO + BB * CC;
        zero2_kernel<<<(ntot + 255) / 256, 256>>>(Q, SZ_ZERO, out, BB * CC);
    }

    adj_kernel<<<1, 256>>>(A, adj);

    // P = adj @ inp0                       [80,300]  K=80
    gemm80<false><<<dim3(1, 3, 1), 256>>>(
        adj, inp, P, nullptr, nullptr, DW, CC, CC, DW, DW, 0, 0);

    // x1 = P @ W_gc1 (pre-activation)      [80,1024] K=300, split 8
    gemm80<false><<<dim3(1, 8, 8), 256>>>(
        P, Wgc1, x1, nullptr, nullptr, 1024, DW, DW, 1024, 1024, 0, 0);

    // Q = adj @ leaky(x1)                  [80,1024] K=80, split 2
    gemm80<false><<<dim3(1, 8, 2), 256>>>(
        adj, x1, Q, nullptr, nullptr, 1024, CC, CC, 1024, 1024, 1, 0);

    // x2 = Q @ W_gc2                       [80,2048] K=1024, split 18 (288 blk)
    gemm80<false><<<dim3(1, 16, 18), 256>>>(
        Q, Wgc2, x2, nullptr, nullptr, 2048, 1024, 1024, 2048, 2048, 0, 0);

    // cls = x2 @ W_cls^T + b_cls           [80,8000] K=2048, split 9 (567 blk)
    gemm80<true><<<dim3(1, 63, 9), 256>>>(
        x2, Wcls, cls, bcls, nullptr, JJ, 2048, 2048, 2048, JJ, 0, 0);

    // t = cls @ b_img                      [80]
    dot_bias_kernel<<<CC, 256>>>(cls, bimg, t, JJ);

    // M = cls @ W_img                      [80,2048] K=8000, split 27 (432 blk)
    gemm80<false><<<dim3(1, 16, 27), 256>>>(
        cls, Wimg, Mm, nullptr, nullptr, 2048, JJ, JJ, 2048, 2048, 0, 0);

    // out^T: C[c,b] = Mm[c,:].feature[b,:] + t[c] -> out[b*80+c]
    //                                      [80,1024] K=2048, split 37 (296 blk)
    gemm80<true><<<dim3(1, 8, 37), 256>>>(
        Mm, feature, out, nullptr, t, BB, 2048, 2048, 2048, CC, 0, 1);
}

// round 10
// speedup vs baseline: 1.5003x; 1.0373x over previous
#include <cuda_runtime.h>
#include <cuda_bf16.h>
#include <cstdint>

// Problem dims
#define BB 1024
#define CC 80
#define DW 300
#define JJ 8000
#define ICH 2048

// ---- scratch layout in one device global (no allocations allowed) ----------
#define OFF_ADJ 0
#define SZ_ADJ  (CC*CC)
#define OFF_P   (OFF_ADJ + SZ_ADJ)
#define SZ_P    (CC*DW)
#define OFF_T   (OFF_P + SZ_P)
#define SZ_T    (CC)
#define OFF_Q   (OFF_T + SZ_T)
#define SZ_Q    (CC*1024)
#define OFF_X1  (OFF_Q + SZ_Q)
#define SZ_X1   (CC*1024)
#define OFF_X2  (OFF_X1 + SZ_X1)
#define SZ_X2   (CC*2048)
#define OFF_CLS (OFF_X2 + SZ_X2)
#define SZ_CLS  (CC*JJ)
#define OFF_M   (OFF_CLS + SZ_CLS)
#define SZ_M    (CC*2048)
#define SZ_ZERO (SZ_Q + SZ_X1 + SZ_X2 + SZ_CLS + SZ_M)
#define SZ_TOT  (OFF_M + SZ_M)

__device__ float g_buf[SZ_TOT];

// ===========================================================================
// helpers
// ===========================================================================
__device__ __forceinline__ uint32_t smem_u32(const void* p) {
    uint32_t a;
    asm("{ .reg .u64 t; cvta.to.shared.u64 t, %1; cvt.u32.u64 %0, t; }"
        : "=r"(a) : "l"(p));
    return a;
}
__device__ __forceinline__ void ldsm4(uint32_t& r0, uint32_t& r1,
                                      uint32_t& r2, uint32_t& r3, uint32_t addr) {
    asm volatile("ldmatrix.sync.aligned.m8n8.x4.shared.b16 {%0,%1,%2,%3}, [%4];"
                 : "=r"(r0), "=r"(r1), "=r"(r2), "=r"(r3) : "r"(addr));
}
__device__ __forceinline__ void mma16816(float* c,
        uint32_t a0, uint32_t a1, uint32_t a2, uint32_t a3,
        uint32_t b0, uint32_t b1) {
    asm volatile("mma.sync.aligned.m16n8k16.row.col.f32.bf16.bf16.f32 "
                 "{%0,%1,%2,%3}, {%4,%5,%6,%7}, {%8,%9}, {%0,%1,%2,%3};"
                 : "+f"(c[0]), "+f"(c[1]), "+f"(c[2]), "+f"(c[3])
                 : "r"(a0), "r"(a1), "r"(a2), "r"(a3), "r"(b0), "r"(b1));
}
__device__ __forceinline__ uint32_t packbf(__nv_bfloat16 a, __nv_bfloat16 b) {
    __nv_bfloat162 t = __halves2bfloat162(a, b);
    return *reinterpret_cast<uint32_t*>(&t);
}
// fp32x4 -> bf16 hi quad + bf16 lo quad (split precision)
__device__ __forceinline__ void split4(float4 v, uint2& hi, uint2& lo) {
    __nv_bfloat16 h0 = __float2bfloat16_rn(v.x);
    __nv_bfloat16 h1 = __float2bfloat16_rn(v.y);
    __nv_bfloat16 h2 = __float2bfloat16_rn(v.z);
    __nv_bfloat16 h3 = __float2bfloat16_rn(v.w);
    __nv_bfloat16 l0 = __float2bfloat16_rn(v.x - __bfloat162float(h0));
    __nv_bfloat16 l1 = __float2bfloat16_rn(v.y - __bfloat162float(h1));
    __nv_bfloat16 l2 = __float2bfloat16_rn(v.z - __bfloat162float(h2));
    __nv_bfloat16 l3 = __float2bfloat16_rn(v.w - __bfloat162float(h3));
    hi.x = packbf(h0, h1); hi.y = packbf(h2, h3);
    lo.x = packbf(l0, l1); lo.y = packbf(l2, l3);
}

// ===========================================================================
// Tensor-core GEMM via mma.sync (HMMA, baseline PTX - works at compute_103):
//   C[80, N] += A[80, K] * op(B), split bf16 (hi/lo, 3 terms), fp32 accum.
// BNK=true: B gmem is [N, K]; false: B is [K, N] (4x4 register transpose).
// Block: 320 threads = 10 warps (5m x 2n). Tile 80 x 64, k-tile 64 fp32.
// Smem rows stride 72 bf16 (144B) -> conflict-free ldmatrix.
// Split-K over gridDim.y; atomicAdd into pre-zeroed C; bias on blockIdx.y==0.
// ===========================================================================
#define HRS 72
#define HA_ELEM (80 * HRS)                       // 5760
#define HB_ELEM (64 * HRS)                       // 4608
#define HBUF_ELEM (2 * HA_ELEM + 2 * HB_ELEM)    // 20736 bf16
#define HS_BYTES (2 * HBUF_ELEM * 2)             // 82944 B

template<bool BNK>
__global__ void __launch_bounds__(320)
hgemm(const float* __restrict__ A, const float* __restrict__ B,
      float* __restrict__ C, const float* __restrict__ bias_n,
      const float* __restrict__ bias_m,
      int N, int K, int lda, int ldb, int ldc, int transC) {
    extern __shared__ __nv_bfloat16 hs[];
    const uint32_t sbase = smem_u32(hs);

    const int tid  = threadIdx.x;
    const int lane = tid & 31;
    const int wid  = tid >> 5;          // 0..9
    const int wm   = wid >> 1;          // 0..4 -> rows wm*16
    const int wn   = wid & 1;           // 0..1 -> cols wn*32
    const int n0   = blockIdx.x * 64;

    const int chunk = (K + gridDim.y - 1) / (int)gridDim.y;
    const int kb = min(K, (int)blockIdx.y * chunk);
    const int ke = min(K, kb + chunk);
    const int ntiles = (ke - kb + 63) >> 6;

    // element offsets within a buffer (bf16 units)
    const uint32_t oAH = 0, oAL = HA_ELEM;
    const uint32_t oBH = 2 * HA_ELEM, oBL = 2 * HA_ELEM + HB_ELEM;

    // ---- staging registers
    uint2 aH[4], aL[4];
    uint2 bH[4], bL[4];

    auto loadA = [&](int k0) {
        #pragma unroll
        for (int i = 0; i < 4; i++) {
            int idx = tid + i * 320;            // 80*16 = 1280 exact
            int row = idx >> 4, c4 = idx & 15;
            int gk = k0 + c4 * 4;
            float4 v = make_float4(0.f, 0.f, 0.f, 0.f);
            if (gk < ke) v = *(const float4*)(A + (size_t)row * lda + gk);
            split4(v, aH[i], aL[i]);
        }
    };
    auto storeA = [&](int buf) {
        __nv_bfloat16* base = hs + buf * HBUF_ELEM;
        #pragma unroll
        for (int i = 0; i < 4; i++) {
            int idx = tid + i * 320;
            int row = idx >> 4, c4 = idx & 15;
            uint32_t off = row * HRS + c4 * 4;
            *(uint2*)(base + oAH + off) = aH[i];
            *(uint2*)(base + oAL + off) = aL[i];
        }
    };
    auto loadB = [&](int k0) {
        if (BNK) {
            #pragma unroll
            for (int i = 0; i < 4; i++) {
                int idx = tid + i * 320;        // need 64*16 = 1024
                if (idx >= 1024) continue;
                int row = idx >> 4, c4 = idx & 15;
                int gn = n0 + row, gk = k0 + c4 * 4;
                float4 v = make_float4(0.f, 0.f, 0.f, 0.f);
                if (gk < ke) v = *(const float4*)(B + (size_t)gn * ldb + gk);
                split4(v, bH[i], bL[i]);
            }
        } else {
            // B[K,N]: groups of 4 k-rows x 4 n-cols, register transpose
            if (tid < 256) {
                int nq = tid & 15, kq = tid >> 4;
                int gn = n0 + nq * 4, gkb = k0 + kq * 4;
                float4 r[4];
                #pragma unroll
                for (int rr = 0; rr < 4; rr++) {
                    int gk = gkb + rr;
                    r[rr] = (gk < ke) ? *(const float4*)(B + (size_t)gk * ldb + gn)
                                      : make_float4(0.f, 0.f, 0.f, 0.f);
                }
                #pragma unroll
                for (int j = 0; j < 4; j++) {
                    float4 kv = make_float4(((float*)&r[0])[j], ((float*)&r[1])[j],
                                            ((float*)&r[2])[j], ((float*)&r[3])[j]);
                    split4(kv, bH[j], bL[j]);
                }
            }
        }
    };
    auto storeB = [&](int buf) {
        __nv_bfloat16* base = hs + buf * HBUF_ELEM;
        if (BNK) {
            #pragma unroll
            for (int i = 0; i < 4; i++) {
                int idx = tid + i * 320;
                if (idx >= 1024) continue;
                int row = idx >> 4, c4 = idx & 15;
                uint32_t off = row * HRS + c4 * 4;
                *(uint2*)(base + oBH + off) = bH[i];
                *(uint2*)(base + oBL + off) = bL[i];
            }
        } else {
            if (tid < 256) {
                int nq = tid & 15, kq = tid >> 4;
                #pragma unroll
                for (int j = 0; j < 4; j++) {
                    uint32_t off = (nq * 4 + j) * HRS + kq * 4;
                    *(uint2*)(base + oBH + off) = bH[j];
                    *(uint2*)(base + oBL + off) = bL[j];
                }
            }
        }
    };

    float acc[4][4];
    #pragma unroll
    for (int i = 0; i < 4; i++)
        #pragma unroll
        for (int j = 0; j < 4; j++) acc[i][j] = 0.f;

    if (ntiles > 0) {
        loadA(kb); loadB(kb);
        storeA(0); storeB(0);
        __syncthreads();
    }

    const int grp = lane >> 3, lr = lane & 7;

    for (int t = 0; t < ntiles; t++) {
        const int cur = t & 1;
        const bool more = (t + 1 < ntiles);
        if (more) { int k0n = kb + (t + 1) * 64; loadA(k0n); loadB(k0n); }

        const uint32_t bufb = sbase + cur * (HBUF_ELEM * 2);
        const uint32_t tA[3] = {bufb + oAH * 2, bufb + oAH * 2, bufb + oAL * 2};
        const uint32_t tB[3] = {bufb + oBH * 2, bufb + oBL * 2, bufb + oBH * 2};

        #pragma unroll
        for (int t3 = 0; t3 < 3; t3++) {
            #pragma unroll
            for (int k16 = 0; k16 < 4; k16++) {
                // A fragment m16k16 (rows wm*16..+15)
                uint32_t a0, a1, a2, a3;
                {
                    uint32_t row = wm * 16 + ((grp & 1) << 3) + lr;
                    uint32_t col = k16 * 16 + ((grp >> 1) << 3);
                    ldsm4(a0, a1, a2, a3, tA[t3] + (row * HRS + col) * 2);
                }
                // B fragments: 4 n8-tiles (cols wn*32..+31)
                uint32_t b[8];
                #pragma unroll
                for (int h = 0; h < 2; h++) {
                    uint32_t row = wn * 32 + h * 16 + ((grp >> 1) << 3) + lr;
                    uint32_t col = k16 * 16 + ((grp & 1) << 3);
                    ldsm4(b[h*4], b[h*4+1], b[h*4+2], b[h*4+3],
                          tB[t3] + (row * HRS + col) * 2);
                }
                #pragma unroll
                for (int nt = 0; nt < 4; nt++)
                    mma16816(acc[nt], a0, a1, a2, a3, b[nt*2], b[nt*2+1]);
            }
        }

        if (more) { storeA(cur ^ 1); storeB(cur ^ 1); }
        __syncthreads();
    }

    // ---- epilogue: acc frag mapping -> atomicAdd into pre-zeroed C
    const bool first = (blockIdx.y == 0);
    const int r0 = wm * 16 + (lane >> 2);
    const int cb = n0 + wn * 32 + (lane & 3) * 2;
    #pragma unroll
    for (int nt = 0; nt < 4; nt++) {
        #pragma unroll
        for (int e = 0; e < 4; e++) {
            int gm = r0 + ((e >> 1) << 3);        // e=0,1 -> r0 ; e=2,3 -> r0+8
            int gn = cb + nt * 8 + (e & 1);
            if (gn >= N) continue;
            float v = acc[nt][e];
            if (first) {
                if (bias_n) v += bias_n[gn];
                if (bias_m) v += bias_m[gm];
            }
            float* dst = transC ? (C + (size_t)gn * ldc + gm)
                                : (C + (size_t)gm * ldc + gn);
            atomicAdd(dst, v);
        }
    }
}

// ===========================================================================
// Small SIMT kernels
// ===========================================================================
__global__ void adj_kernel(const float* __restrict__ A, float* __restrict__ adj) {
    __shared__ float D[CC];
    int tid = threadIdx.x;
    if (tid < CC) {
        float s = 0.f;
        #pragma unroll 4
        for (int j = 0; j < CC; j++) s += A[tid * CC + j];
        D[tid] = 1.0f / sqrtf(s);
    }
    __syncthreads();
    for (int idx = tid; idx < CC * CC; idx += blockDim.x) {
        int i = idx / CC, j = idx % CC;
        adj[idx] = D[i] * A[j * CC + i] * D[j];
    }
}

__global__ void zero2_kernel(float* __restrict__ a, int na,
                             float* __restrict__ b, int nb) {
    int i = blockIdx.x * blockDim.x + threadIdx.x;
    if (i < na) a[i] = 0.f;
    else if (i - na < nb) b[i - na] = 0.f;
}

__global__ void dot_bias_kernel(const float* __restrict__ cls,
                                const float* __restrict__ b,
                                float* __restrict__ t, int J) {
    int c = blockIdx.x;
    float s = 0.f;
    for (int j = threadIdx.x; j < J; j += blockDim.x)
        s += cls[c * J + j] * b[j];
    #pragma unroll
    for (int o = 16; o > 0; o >>= 1) s += __shfl_down_sync(0xFFFFFFFFu, s, o);
    __shared__ float red[8];
    if ((threadIdx.x & 31) == 0) red[threadIdx.x >> 5] = s;
    __syncthreads();
    if (threadIdx.x == 0) {
        float tot = 0.f;
        #pragma unroll
        for (int w = 0; w < 8; w++) tot += red[w];
        t[c] = tot;
    }
}

// M=80 SIMT GEMM (fp32x2), double-buffered -- tiny GCN chain only.
template<bool TB>
__global__ void __launch_bounds__(256, 2)
gemm80(const float* __restrict__ A, const float* __restrict__ B,
       float* __restrict__ C, const float* __restrict__ bias_n,
       const float* __restrict__ bias_m,
       int N, int K, int lda, int ldb, int ldc, int leaky_b, int transC) {
    __shared__ float  As[2][16][82];
    __shared__ float2 Bs[2][16][129];

    const int tid = threadIdx.x;
    const int tr = tid >> 5;
    const int tc = tid & 31;
    const int n0 = blockIdx.y * 128;

    const int chunk = (K + gridDim.z - 1) / (int)gridDim.z;
    const int kb = min(K, (int)blockIdx.z * chunk);
    const int ke = min(K, kb + chunk);
    const int ntiles = (ke - kb + 15) >> 4;

    float aR[5];
    float bR[8];

    auto loadA = [&](int k0) {
        #pragma unroll
        for (int t = 0; t < 5; t++) {
            int idx = tid + t * 256;
            int m = idx >> 4, k = idx & 15;
            int gk = k0 + k;
            aR[t] = (gk < ke) ? A[(size_t)m * lda + gk] : 0.f;
        }
    };
    auto storeA = [&](int buf) {
        #pragma unroll
        for (int t = 0; t < 5; t++) {
            int idx = tid + t * 256;
            int m = idx >> 4, k = idx & 15;
            As[buf][k][m] = aR[t];
        }
    };
    auto loadB = [&](int k0) {
        if (TB) {
            #pragma unroll
            for (int t = 0; t < 8; t++) {
                int idx = tid + t * 256;
                int k = idx & 15, n = idx >> 4;
                int gk = k0 + k, gn = n0 + n;
                float v = 0.f;
                if (gk < ke && gn < N) v = B[(size_t)gn * ldb + gk];
                bR[t] = v;
            }
        } else {
            #pragma unroll
            for (int t = 0; t < 8; t++) {
                int idx = tid + t * 256;
                int k = idx >> 7, n = idx & 127;
                int gk = k0 + k, gn = n0 + n;
                float v = 0.f;
                if (gk < ke && gn < N) v = B[(size_t)gk * ldb + gn];
                if (leaky_b) v = v > 0.f ? v : 0.2f * v;
                bR[t] = v;
            }
        }
    };
    auto storeB = [&](int buf) {
        #pragma unroll
        for (int t = 0; t < 8; t++) {
            int idx = tid + t * 256;
            int k, n;
            if (TB) { k = idx & 15; n = idx >> 4; }
            else    { k = idx >> 7; n = idx & 127; }
            Bs[buf][k][n] = make_float2(bR[t], bR[t]);
        }
    };

    unsigned long long acc[5][4];
    #pragma unroll
    for (int i = 0; i < 5; i++)
        #pragma unroll
        for (int j = 0; j < 4; j++) acc[i][j] = 0ULL;

    if (ntiles > 0) {
        loadA(kb); loadB(kb);
        storeA(0); storeB(0);
        __syncthreads();
    }

    for (int t = 0; t < ntiles; t++) {
        const int cur = t & 1;
        const bool more = (t + 1 < ntiles);
        if (more) { int k0n = kb + (t + 1) * 16; loadA(k0n); loadB(k0n); }

        #pragma unroll
        for (int k = 0; k < 16; k++) {
            unsigned long long a2[5], b2[4];
            const unsigned long long* ap =
                (const unsigned long long*)&As[cur][k][tr * 10];
            #pragma unroll
            for (int i = 0; i < 5; i++) a2[i] = ap[i];
            #pragma unroll
            for (int j = 0; j < 4; j++)
                b2[j] = *(const unsigned long long*)&Bs[cur][k][tc + 32 * j];
            #pragma unroll
            for (int i = 0; i < 5; i++)
                #pragma unroll
                for (int j = 0; j < 4; j++)
                    asm("fma.rn.f32x2 %0, %1, %2, %0;"
                        : "+l"(acc[i][j]) : "l"(a2[i]), "l"(b2[j]));
        }

        if (more) { storeA(cur ^ 1); storeB(cur ^ 1); }
        __syncthreads();
    }

    const bool split = (gridDim.z > 1);
    const bool first = (blockIdx.z == 0);
    #pragma unroll
    for (int i = 0; i < 5; i++) {
        #pragma unroll
        for (int j = 0; j < 4; j++) {
            int gn = n0 + tc + 32 * j;
            if (gn >= N) continue;
            unsigned int ulo, uhi;
            asm("mov.b64 {%0, %1}, %2;" : "=r"(ulo), "=r"(uhi) : "l"(acc[i][j]));
            float vals[2] = {__uint_as_float(ulo), __uint_as_float(uhi)};
            #pragma unroll
            for (int p = 0; p < 2; p++) {
                int gm = tr * 10 + 2 * i + p;
                float v = vals[p];
                if (first) {
                    if (bias_n) v += bias_n[gn];
                    if (bias_m) v += bias_m[gm];
                }
                float* dst = transC ? (C + (size_t)gn * ldc + gm)
                                    : (C + (size_t)gm * ldc + gn);
                if (split) atomicAdd(dst, v);
                else *dst = v;
            }
        }
    }
}

// ===========================================================================
extern "C" void kernel_launch(void* const* d_in, const int* in_sizes, int n_in,
                              void* d_out, int out_size) {
    const float* feature = (const float*)d_in[0];   // [1024, 2048]
    const float* inp     = (const float*)d_in[1];   // [1, 80, 300]
    const float* A       = (const float*)d_in[2];   // [80, 80]
    const float* Wgc1    = (const float*)d_in[3];   // [300, 1024]
    const float* Wgc2    = (const float*)d_in[4];   // [1024, 2048]
    const float* Wimg    = (const float*)d_in[5];   // [8000, 2048]
    const float* bimg    = (const float*)d_in[6];   // [8000]
    const float* Wcls    = (const float*)d_in[7];   // [8000, 2048]
    const float* bcls    = (const float*)d_in[8];   // [8000]
    float* out = (float*)d_out;                     // [1024, 80] row-major

    float* buf;
    cudaGetSymbolAddress((void**)&buf, g_buf);
    float* adj = buf + OFF_ADJ;
    float* P   = buf + OFF_P;
    float* t   = buf + OFF_T;
    float* Q   = buf + OFF_Q;
    float* x1  = buf + OFF_X1;
    float* x2  = buf + OFF_X2;
    float* cls = buf + OFF_CLS;
    float* Mm  = buf + OFF_M;

    cudaFuncSetAttribute(hgemm<false>,
                         cudaFuncAttributeMaxDynamicSharedMemorySize, HS_BYTES);
    cudaFuncSetAttribute(hgemm<true>,
                         cudaFuncAttributeMaxDynamicSharedMemorySize, HS_BYTES);

    // Zero split-K targets (Q,x1,x2,cls,Mm contiguous) + out
    {
        int ntot = SZ_ZERO + BB * CC;
        zero2_kernel<<<(ntot + 255) / 256, 256>>>(Q, SZ_ZERO, out, BB * CC);
    }

    adj_kernel<<<1, 256>>>(A, adj);

    // P = adj @ inp0                       [80,300]  K=80     (SIMT)
    gemm80<false><<<dim3(1, 3, 1), 256>>>(
        adj, inp, P, nullptr, nullptr, DW, CC, CC, DW, DW, 0, 0);

    // x1 = P @ W_gc1 (pre-activation)      [80,1024] K=300, split 8 (SIMT)
    gemm80<false><<<dim3(1, 8, 8), 256>>>(
        P, Wgc1, x1, nullptr, nullptr, 1024, DW, DW, 1024, 1024, 0, 0);

    // Q = adj @ leaky(x1)                  [80,1024] K=80, split 2 (SIMT)
    gemm80<false><<<dim3(1, 8, 2), 256>>>(
        adj, x1, Q, nullptr, nullptr, 1024, CC, CC, 1024, 1024, 1, 0);

    // x2 = Q @ W_gc2                       [80,2048] K=1024  (HMMA, B=[K,N])
    hgemm<false><<<dim3(32, 4), 320, HS_BYTES>>>(
        Q, Wgc2, x2, nullptr, nullptr, 2048, 1024, 1024, 2048, 2048, 0);

    // cls = x2 @ W_cls^T + b_cls           [80,8000] K=2048  (HMMA, B=[N,K])
    hgemm<true><<<dim3(125, 4), 320, HS_BYTES>>>(
        x2, Wcls, cls, bcls, nullptr, JJ, 2048, 2048, 2048, JJ, 0);

    // t = cls @ b_img                      [80]
    dot_bias_kernel<<<CC, 256>>>(cls, bimg, t, JJ);

    // M = cls @ W_img                      [80,2048] K=8000  (HMMA, B=[K,N])
    hgemm<false><<<dim3(32, 5), 320, HS_BYTES>>>(
        cls, Wimg, Mm, nullptr, nullptr, 2048, JJ, JJ, 2048, 2048, 0);

    // out^T: C[c,b] = Mm[c,:].feature[b,:] + t[c] -> out[b*80+c]
    //                                      [80,1024] K=2048  (HMMA, B=[N,K])
    hgemm<true><<<dim3(16, 8), 320, HS_BYTES>>>(
        Mm, feature, out, nullptr, t, BB, 2048, 2048, 2048, CC, 1);
}

// round 11
// speedup vs baseline: 1.9521x; 1.3011x over previous
#include <cuda_runtime.h>
#include <cuda_bf16.h>
#include <cstdint>

// Problem dims
#define BB 1024
#define CC 80
#define DW 300
#define DWP 304          // padded DW for aligned float4 rows
#define JJ 8000
#define ICH 2048

// ---- scratch layout in one device global (no allocations allowed) ----------
// Non-zeroed: adj, t. Zeroed contiguous (all hgemm atomic targets): P..M
#define OFF_ADJ 0
#define SZ_ADJ  (CC*CC)
#define OFF_T   (OFF_ADJ + SZ_ADJ)
#define SZ_T    (CC)
#define OFF_P   (OFF_T + SZ_T)
#define SZ_P    (CC*DWP)
#define OFF_Q   (OFF_P + SZ_P)
#define SZ_Q    (CC*1024)
#define OFF_X1  (OFF_Q + SZ_Q)
#define SZ_X1   (CC*1024)
#define OFF_X2  (OFF_X1 + SZ_X1)
#define SZ_X2   (CC*2048)
#define OFF_CLS (OFF_X2 + SZ_X2)
#define SZ_CLS  (CC*JJ)
#define OFF_M   (OFF_CLS + SZ_CLS)
#define SZ_M    (CC*2048)
#define SZ_ZERO (SZ_P + SZ_Q + SZ_X1 + SZ_X2 + SZ_CLS + SZ_M)
#define SZ_TOT  (OFF_M + SZ_M)

__device__ float g_buf[SZ_TOT];

// ===========================================================================
// helpers
// ===========================================================================
__device__ __forceinline__ uint32_t smem_u32(const void* p) {
    uint32_t a;
    asm("{ .reg .u64 t; cvta.to.shared.u64 t, %1; cvt.u32.u64 %0, t; }"
        : "=r"(a) : "l"(p));
    return a;
}
__device__ __forceinline__ void ldsm4(uint32_t& r0, uint32_t& r1,
                                      uint32_t& r2, uint32_t& r3, uint32_t addr) {
    asm volatile("ldmatrix.sync.aligned.m8n8.x4.shared.b16 {%0,%1,%2,%3}, [%4];"
                 : "=r"(r0), "=r"(r1), "=r"(r2), "=r"(r3) : "r"(addr));
}
__device__ __forceinline__ void mma16816(float* c,
        uint32_t a0, uint32_t a1, uint32_t a2, uint32_t a3,
        uint32_t b0, uint32_t b1) {
    asm volatile("mma.sync.aligned.m16n8k16.row.col.f32.bf16.bf16.f32 "
                 "{%0,%1,%2,%3}, {%4,%5,%6,%7}, {%8,%9}, {%0,%1,%2,%3};"
                 : "+f"(c[0]), "+f"(c[1]), "+f"(c[2]), "+f"(c[3])
                 : "r"(a0), "r"(a1), "r"(a2), "r"(a3), "r"(b0), "r"(b1));
}
__device__ __forceinline__ uint32_t packbf(__nv_bfloat16 a, __nv_bfloat16 b) {
    __nv_bfloat162 t = __halves2bfloat162(a, b);
    return *reinterpret_cast<uint32_t*>(&t);
}
// fp32x4 -> bf16 hi quad + bf16 lo quad (split precision)
__device__ __forceinline__ void split4(float4 v, uint2& hi, uint2& lo) {
    __nv_bfloat16 h0 = __float2bfloat16_rn(v.x);
    __nv_bfloat16 h1 = __float2bfloat16_rn(v.y);
    __nv_bfloat16 h2 = __float2bfloat16_rn(v.z);
    __nv_bfloat16 h3 = __float2bfloat16_rn(v.w);
    __nv_bfloat16 l0 = __float2bfloat16_rn(v.x - __bfloat162float(h0));
    __nv_bfloat16 l1 = __float2bfloat16_rn(v.y - __bfloat162float(h1));
    __nv_bfloat16 l2 = __float2bfloat16_rn(v.z - __bfloat162float(h2));
    __nv_bfloat16 l3 = __float2bfloat16_rn(v.w - __bfloat162float(h3));
    hi.x = packbf(h0, h1); hi.y = packbf(h2, h3);
    lo.x = packbf(l0, l1); lo.y = packbf(l2, l3);
}
__device__ __forceinline__ float4 leaky4(float4 v) {
    v.x = v.x > 0.f ? v.x : 0.2f * v.x;
    v.y = v.y > 0.f ? v.y : 0.2f * v.y;
    v.z = v.z > 0.f ? v.z : 0.2f * v.z;
    v.w = v.w > 0.f ? v.w : 0.2f * v.w;
    return v;
}

// ===========================================================================
// Tensor-core GEMM via mma.sync (HMMA; baseline PTX, safe at compute_103):
//   C[80, N] += A[80, K] * op(B), split bf16 (hi/lo, 3 terms), fp32 accum.
// Tile 80 x 128, k-tile 64 fp32. 320 threads = 10 warps (5m x 2n); each warp:
// m16 x n64 -> 8 independent acc chains.  BNK=true: B is [N,K]; false: [K,N]
// (4x4 register transpose at load; optional fused leaky).  Smem row stride 72
// bf16 -> conflict-free ldmatrix.  Split-K over gridDim.y (chunk % 4 == 0);
// atomicAdd into pre-zeroed C; bias on blockIdx.y==0.  Kb limits B's K reads
// (for padded-K calls); A beyond Kb must be zero-padded memory.
// ===========================================================================
#define HRS 72
#define HA_ELEM (80 * HRS)                        // 5760
#define HB_ELEM (128 * HRS)                       // 9216
#define HBUF_ELEM (2 * HA_ELEM + 2 * HB_ELEM)     // 29952 bf16
#define HS_BYTES (2 * HBUF_ELEM * 2)              // 119808 B

template<bool BNK>
__global__ void __launch_bounds__(320)
hgemm(const float* __restrict__ A, const float* __restrict__ B,
      float* __restrict__ C, const float* __restrict__ bias_n,
      const float* __restrict__ bias_m,
      int N, int K, int Kb, int lda, int ldb, int ldc, int leaky_b, int transC) {
    extern __shared__ __nv_bfloat16 hs[];
    const uint32_t sbase = smem_u32(hs);

    const int tid  = threadIdx.x;
    const int lane = tid & 31;
    const int wid  = tid >> 5;          // 0..9
    const int wm   = wid >> 1;          // 0..4 -> rows wm*16
    const int wn   = wid & 1;           // 0..1 -> cols wn*64
    const int n0   = blockIdx.x * 128;

    const int chunk = (K + gridDim.y - 1) / (int)gridDim.y;
    const int kb = min(K, (int)blockIdx.y * chunk);
    const int ke = min(K, kb + chunk);
    const int ntiles = (ke - kb + 63) >> 6;
    const int keB = min(ke, Kb);

    const uint32_t oAH = 0, oAL = HA_ELEM;
    const uint32_t oBH = 2 * HA_ELEM, oBL = 2 * HA_ELEM + HB_ELEM;

    // ---- staging registers
    uint2 aH[4], aL[4];
    uint2 bH[7], bL[7];

    auto loadA = [&](int k0) {
        #pragma unroll
        for (int i = 0; i < 4; i++) {
            int idx = tid + i * 320;            // 80*16 = 1280 exact
            int row = idx >> 4, c4 = idx & 15;
            int gk = k0 + c4 * 4;
            float4 v = make_float4(0.f, 0.f, 0.f, 0.f);
            if (gk < ke) v = *(const float4*)(A + (size_t)row * lda + gk);
            split4(v, aH[i], aL[i]);
        }
    };
    auto storeA = [&](int buf) {
        __nv_bfloat16* base = hs + buf * HBUF_ELEM;
        #pragma unroll
        for (int i = 0; i < 4; i++) {
            int idx = tid + i * 320;
            int row = idx >> 4, c4 = idx & 15;
            uint32_t off = row * HRS + c4 * 4;
            *(uint2*)(base + oAH + off) = aH[i];
            *(uint2*)(base + oAL + off) = aL[i];
        }
    };
    auto loadB = [&](int k0) {
        if (BNK) {
            #pragma unroll
            for (int i = 0; i < 7; i++) {
                int idx = tid + i * 320;        // need 128*16 = 2048
                if (idx >= 2048) continue;
                int row = idx >> 4, c4 = idx & 15;
                int gn = n0 + row, gk = k0 + c4 * 4;
                float4 v = make_float4(0.f, 0.f, 0.f, 0.f);
                if (gk < keB && gn < N)
                    v = *(const float4*)(B + (size_t)gn * ldb + gk);
                split4(v, bH[i], bL[i]);
            }
        } else {
            // B[K,N]: groups of 4 k-rows x 4 n-cols, register transpose
            #pragma unroll
            for (int i = 0; i < 2; i++) {
                int idx = tid + i * 320;        // need 32*16 = 512 groups
                if (idx >= 512) continue;
                int nq = idx & 31, kq = idx >> 5;
                int gn = n0 + nq * 4, gkb = k0 + kq * 4;
                float4 r[4];
                #pragma unroll
                for (int rr = 0; rr < 4; rr++) {
                    int gk = gkb + rr;
                    float4 v = make_float4(0.f, 0.f, 0.f, 0.f);
                    if (gk < keB && gn < N)
                        v = *(const float4*)(B + (size_t)gk * ldb + gn);
                    if (leaky_b) v = leaky4(v);
                    r[rr] = v;
                }
                #pragma unroll
                for (int j = 0; j < 4; j++) {
                    float4 kv = make_float4(((float*)&r[0])[j], ((float*)&r[1])[j],
                                            ((float*)&r[2])[j], ((float*)&r[3])[j]);
                    split4(kv, bH[i * 4 + j < 7 ? i * 4 + j : 6],
                              bL[i * 4 + j < 7 ? i * 4 + j : 6]);
                    // note: i*4+j ranges 0..7; pack 8th into slot reuse below
                    if (i * 4 + j == 7) { bH[6] = bH[6]; }  // (unreachable; see storeB)
                }
            }
        }
    };
    // For BNK=false we need 8 staging slots (2 iters x 4); fold slot 7 into a
    // dedicated pair to keep register arrays simple:
    uint2 bH7, bL7;
    auto loadB_f = [&](int k0) {
        #pragma unroll
        for (int i = 0; i < 2; i++) {
            int idx = tid + i * 320;
            if (idx >= 512) continue;
            int nq = idx & 31, kq = idx >> 5;
            int gn = n0 + nq * 4, gkb = k0 + kq * 4;
            float4 r[4];
            #pragma unroll
            for (int rr = 0; rr < 4; rr++) {
                int gk = gkb + rr;
                float4 v = make_float4(0.f, 0.f, 0.f, 0.f);
                if (gk < keB && gn < N)
                    v = *(const float4*)(B + (size_t)gk * ldb + gn);
                if (leaky_b) v = leaky4(v);
                r[rr] = v;
            }
            #pragma unroll
            for (int j = 0; j < 4; j++) {
                float4 kv = make_float4(((float*)&r[0])[j], ((float*)&r[1])[j],
                                        ((float*)&r[2])[j], ((float*)&r[3])[j]);
                int s = i * 4 + j;
                if (s < 7) split4(kv, bH[s], bL[s]);
                else       split4(kv, bH7, bL7);
            }
        }
    };
    auto storeB = [&](int buf) {
        __nv_bfloat16* base = hs + buf * HBUF_ELEM;
        if (BNK) {
            #pragma unroll
            for (int i = 0; i < 7; i++) {
                int idx = tid + i * 320;
                if (idx >= 2048) continue;
                int row = idx >> 4, c4 = idx & 15;
                uint32_t off = row * HRS + c4 * 4;
                *(uint2*)(base + oBH + off) = bH[i];
                *(uint2*)(base + oBL + off) = bL[i];
            }
        } else {
            #pragma unroll
            for (int i = 0; i < 2; i++) {
                int idx = tid + i * 320;
                if (idx >= 512) continue;
                int nq = idx & 31, kq = idx >> 5;
                #pragma unroll
                for (int j = 0; j < 4; j++) {
                    int s = i * 4 + j;
                    uint32_t off = (nq * 4 + j) * HRS + kq * 4;
                    *(uint2*)(base + oBH + off) = (s < 7) ? bH[s] : bH7;
                    *(uint2*)(base + oBL + off) = (s < 7) ? bL[s] : bL7;
                }
            }
        }
    };
    auto loadBx = [&](int k0) { if (BNK) loadB(k0); else loadB_f(k0); };

    float acc[8][4];
    #pragma unroll
    for (int i = 0; i < 8; i++)
        #pragma unroll
        for (int j = 0; j < 4; j++) acc[i][j] = 0.f;

    if (ntiles > 0) {
        loadA(kb); loadBx(kb);
        storeA(0); storeB(0);
        __syncthreads();
    }

    const int grp = lane >> 3, lr = lane & 7;

    for (int t = 0; t < ntiles; t++) {
        const int cur = t & 1;
        const bool more = (t + 1 < ntiles);
        if (more) { int k0n = kb + (t + 1) * 64; loadA(k0n); loadBx(k0n); }

        const uint32_t bufb = sbase + cur * (HBUF_ELEM * 2);
        const uint32_t tA[3] = {bufb + oAH * 2, bufb + oAH * 2, bufb + oAL * 2};
        const uint32_t tB[3] = {bufb + oBH * 2, bufb + oBL * 2, bufb + oBH * 2};

        #pragma unroll
        for (int t3 = 0; t3 < 3; t3++) {
            #pragma unroll
            for (int k16 = 0; k16 < 4; k16++) {
                uint32_t a0, a1, a2, a3;
                {
                    uint32_t row = wm * 16 + ((grp & 1) << 3) + lr;
                    uint32_t col = k16 * 16 + ((grp >> 1) << 3);
                    ldsm4(a0, a1, a2, a3, tA[t3] + (row * HRS + col) * 2);
                }
                uint32_t b[16];
                #pragma unroll
                for (int h = 0; h < 4; h++) {
                    uint32_t row = wn * 64 + h * 16 + ((grp >> 1) << 3) + lr;
                    uint32_t col = k16 * 16 + ((grp & 1) << 3);
                    ldsm4(b[h*4], b[h*4+1], b[h*4+2], b[h*4+3],
                          tB[t3] + (row * HRS + col) * 2);
                }
                #pragma unroll
                for (int nt = 0; nt < 8; nt++)
                    mma16816(acc[nt], a0, a1, a2, a3, b[nt*2], b[nt*2+1]);
            }
        }

        if (more) { storeA(cur ^ 1); storeB(cur ^ 1); }
        __syncthreads();
    }

    // ---- epilogue
    const bool first = (blockIdx.y == 0);
    const int r0 = wm * 16 + (lane >> 2);
    const int cb = n0 + wn * 64 + (lane & 3) * 2;
    #pragma unroll
    for (int nt = 0; nt < 8; nt++) {
        #pragma unroll
        for (int e = 0; e < 4; e++) {
            int gm = r0 + ((e >> 1) << 3);
            int gn = cb + nt * 8 + (e & 1);
            if (gn >= N) continue;
            float v = acc[nt][e];
            if (first) {
                if (bias_n) v += bias_n[gn];
                if (bias_m) v += bias_m[gm];
            }
            float* dst = transC ? (C + (size_t)gn * ldc + gm)
                                : (C + (size_t)gm * ldc + gn);
            atomicAdd(dst, v);
        }
    }
}

// ===========================================================================
// Small kernels
// ===========================================================================
__global__ void adj_kernel(const float* __restrict__ A, float* __restrict__ adj) {
    __shared__ float D[CC];
    int tid = threadIdx.x;
    if (tid < CC) {
        float s = 0.f;
        #pragma unroll 4
        for (int j = 0; j < CC; j++) s += A[tid * CC + j];
        D[tid] = 1.0f / sqrtf(s);
    }
    __syncthreads();
    for (int idx = tid; idx < CC * CC; idx += blockDim.x) {
        int i = idx / CC, j = idx % CC;
        adj[idx] = D[i] * A[j * CC + i] * D[j];
    }
}

__global__ void zero2_kernel(float* __restrict__ a, int na,
                             float* __restrict__ b, int nb) {
    int i = blockIdx.x * blockDim.x + threadIdx.x;
    if (i < na) a[i] = 0.f;
    else if (i - na < nb) b[i - na] = 0.f;
}

__global__ void dot_bias_kernel(const float* __restrict__ cls,
                                const float* __restrict__ b,
                                float* __restrict__ t, int J) {
    int c = blockIdx.x;
    float s = 0.f;
    for (int j = threadIdx.x; j < J; j += blockDim.x)
        s += cls[c * J + j] * b[j];
    #pragma unroll
    for (int o = 16; o > 0; o >>= 1) s += __shfl_down_sync(0xFFFFFFFFu, s, o);
    __shared__ float red[8];
    if ((threadIdx.x & 31) == 0) red[threadIdx.x >> 5] = s;
    __syncthreads();
    if (threadIdx.x == 0) {
        float tot = 0.f;
        #pragma unroll
        for (int w = 0; w < 8; w++) tot += red[w];
        t[c] = tot;
    }
}

// ===========================================================================
extern "C" void kernel_launch(void* const* d_in, const int* in_sizes, int n_in,
                              void* d_out, int out_size) {
    const float* feature = (const float*)d_in[0];   // [1024, 2048]
    const float* inp     = (const float*)d_in[1];   // [1, 80, 300]
    const float* A       = (const float*)d_in[2];   // [80, 80]
    const float* Wgc1    = (const float*)d_in[3];   // [300, 1024]
    const float* Wgc2    = (const float*)d_in[4];   // [1024, 2048]
    const float* Wimg    = (const float*)d_in[5];   // [8000, 2048]
    const float* bimg    = (const float*)d_in[6];   // [8000]
    const float* Wcls    = (const float*)d_in[7];   // [8000, 2048]
    const float* bcls    = (const float*)d_in[8];   // [8000]
    float* out = (float*)d_out;                     // [1024, 80] row-major

    float* buf;
    cudaGetSymbolAddress((void**)&buf, g_buf);
    float* adj = buf + OFF_ADJ;
    float* t   = buf + OFF_T;
    float* P   = buf + OFF_P;
    float* Q   = buf + OFF_Q;
    float* x1  = buf + OFF_X1;
    float* x2  = buf + OFF_X2;
    float* cls = buf + OFF_CLS;
    float* Mm  = buf + OFF_M;

    cudaFuncSetAttribute(hgemm<false>,
                         cudaFuncAttributeMaxDynamicSharedMemorySize, HS_BYTES);
    cudaFuncSetAttribute(hgemm<true>,
                         cudaFuncAttributeMaxDynamicSharedMemorySize, HS_BYTES);

    // Zero all hgemm targets (P..M contiguous) + out, one launch.
    {
        int ntot = SZ_ZERO + BB * CC;
        zero2_kernel<<<(ntot + 255) / 256, 256>>>(P, SZ_ZERO, out, BB * CC);
    }

    adj_kernel<<<1, 256>>>(A, adj);

    // P = adj @ inp0                 [80,300]  K=80      (P padded to ld 304)
    hgemm<false><<<dim3(3, 1), 320, HS_BYTES>>>(
        adj, inp, P, nullptr, nullptr, DW, CC, CC, CC, DW, DWP, 0, 0);

    // x1 = P @ W_gc1                 [80,1024] K=304 pad (Kb=300), split 2
    hgemm<false><<<dim3(8, 2), 320, HS_BYTES>>>(
        P, Wgc1, x1, nullptr, nullptr, 1024, DWP, DW, DWP, 1024, 1024, 0, 0);

    // Q = adj @ leaky(x1)            [80,1024] K=80, split 2 (chunk 40)
    hgemm<false><<<dim3(8, 2), 320, HS_BYTES>>>(
        adj, x1, Q, nullptr, nullptr, 1024, CC, CC, CC, 1024, 1024, 1, 0);

    // x2 = Q @ W_gc2                 [80,2048] K=1024, split 8 (chunk 128)
    hgemm<false><<<dim3(16, 8), 320, HS_BYTES>>>(
        Q, Wgc2, x2, nullptr, nullptr, 2048, 1024, 1024, 1024, 2048, 2048, 0, 0);

    // cls = x2 @ W_cls^T + b_cls     [80,8000] K=2048, split 2 (chunk 1024)
    hgemm<true><<<dim3(63, 2), 320, HS_BYTES>>>(
        x2, Wcls, cls, bcls, nullptr, JJ, 2048, 2048, 2048, 2048, JJ, 0, 0);

    // t = cls @ b_img                [80]
    dot_bias_kernel<<<CC, 256>>>(cls, bimg, t, JJ);

    // M = cls @ W_img                [80,2048] K=8000, split 8 (chunk 1000)
    hgemm<false><<<dim3(16, 8), 320, HS_BYTES>>>(
        cls, Wimg, Mm, nullptr, nullptr, 2048, JJ, JJ, JJ, 2048, 2048, 0, 0);

    // out^T: C[c,b] = Mm[c,:].feature[b,:] + t[c] -> out[b*80+c]
    //                                [80,1024] K=2048, split 16 (chunk 128)
    hgemm<true><<<dim3(8, 16), 320, HS_BYTES>>>(
        Mm, feature, out, nullptr, t, BB, 2048, 2048, 2048, 2048, CC, 0, 1);
}

// round 12
// speedup vs baseline: 2.0516x; 1.0510x over previous
#include <cuda_runtime.h>
#include <cuda_bf16.h>
#include <cstdint>

// Problem dims
#define BB 1024
#define CC 80
#define DW 300
#define DWP 304          // padded DW for aligned float4 rows
#define JJ 8000
#define ICH 2048

// ---- scratch layout in one device global (no allocations allowed) ----------
// Non-zeroed: adj, t. Zeroed contiguous (all hgemm atomic targets): P..M
#define OFF_ADJ 0
#define SZ_ADJ  (CC*CC)
#define OFF_T   (OFF_ADJ + SZ_ADJ)
#define SZ_T    (CC)
#define OFF_P   (OFF_T + SZ_T)
#define SZ_P    (CC*DWP)
#define OFF_Q   (OFF_P + SZ_P)
#define SZ_Q    (CC*1024)
#define OFF_X1  (OFF_Q + SZ_Q)
#define SZ_X1   (CC*1024)
#define OFF_X2  (OFF_X1 + SZ_X1)
#define SZ_X2   (CC*2048)
#define OFF_CLS (OFF_X2 + SZ_X2)
#define SZ_CLS  (CC*JJ)
#define OFF_M   (OFF_CLS + SZ_CLS)
#define SZ_M    (CC*2048)
#define SZ_ZERO (SZ_P + SZ_Q + SZ_X1 + SZ_X2 + SZ_CLS + SZ_M)
#define SZ_TOT  (OFF_M + SZ_M)

__device__ float g_buf[SZ_TOT];

// ===========================================================================
// helpers
// ===========================================================================
__device__ __forceinline__ uint32_t smem_u32(const void* p) {
    uint32_t a;
    asm("{ .reg .u64 t; cvta.to.shared.u64 t, %1; cvt.u32.u64 %0, t; }"
        : "=r"(a) : "l"(p));
    return a;
}
__device__ __forceinline__ void ldsm4(uint32_t& r0, uint32_t& r1,
                                      uint32_t& r2, uint32_t& r3, uint32_t addr) {
    asm volatile("ldmatrix.sync.aligned.m8n8.x4.shared.b16 {%0,%1,%2,%3}, [%4];"
                 : "=r"(r0), "=r"(r1), "=r"(r2), "=r"(r3) : "r"(addr));
}
__device__ __forceinline__ void mma16816(float* c,
        uint32_t a0, uint32_t a1, uint32_t a2, uint32_t a3,
        uint32_t b0, uint32_t b1) {
    asm volatile("mma.sync.aligned.m16n8k16.row.col.f32.bf16.bf16.f32 "
                 "{%0,%1,%2,%3}, {%4,%5,%6,%7}, {%8,%9}, {%0,%1,%2,%3};"
                 : "+f"(c[0]), "+f"(c[1]), "+f"(c[2]), "+f"(c[3])
                 : "r"(a0), "r"(a1), "r"(a2), "r"(a3), "r"(b0), "r"(b1));
}
__device__ __forceinline__ uint32_t packbf(__nv_bfloat16 a, __nv_bfloat16 b) {
    __nv_bfloat162 t = __halves2bfloat162(a, b);
    return *reinterpret_cast<uint32_t*>(&t);
}
// fp32x4 -> bf16 hi quad + bf16 lo quad (split precision)
__device__ __forceinline__ void split4(float4 v, uint2& hi, uint2& lo) {
    __nv_bfloat16 h0 = __float2bfloat16_rn(v.x);
    __nv_bfloat16 h1 = __float2bfloat16_rn(v.y);
    __nv_bfloat16 h2 = __float2bfloat16_rn(v.z);
    __nv_bfloat16 h3 = __float2bfloat16_rn(v.w);
    __nv_bfloat16 l0 = __float2bfloat16_rn(v.x - __bfloat162float(h0));
    __nv_bfloat16 l1 = __float2bfloat16_rn(v.y - __bfloat162float(h1));
    __nv_bfloat16 l2 = __float2bfloat16_rn(v.z - __bfloat162float(h2));
    __nv_bfloat16 l3 = __float2bfloat16_rn(v.w - __bfloat162float(h3));
    hi.x = packbf(h0, h1); hi.y = packbf(h2, h3);
    lo.x = packbf(l0, l1); lo.y = packbf(l2, l3);
}
__device__ __forceinline__ float4 leaky4(float4 v) {
    v.x = v.x > 0.f ? v.x : 0.2f * v.x;
    v.y = v.y > 0.f ? v.y : 0.2f * v.y;
    v.z = v.z > 0.f ? v.z : 0.2f * v.z;
    v.w = v.w > 0.f ? v.w : 0.2f * v.w;
    return v;
}

// ===========================================================================
// Tensor-core GEMM via mma.sync (HMMA; baseline PTX, safe at compute_103):
//   C[80, N] += A[80, K] * op(B), split bf16 (hi/lo, 3 terms), fp32 accum.
// Tile 80 x 128, k-tile 64 fp32. 320 threads = 10 warps (5m x 2n); each warp
// m16 x n64 -> 8 independent acc chains. The 3-term loop is NOT unrolled
// (small I$ body; descriptor bases chosen arithmetically, no local arrays).
// BNK=true: B is [N,K]; false: [K,N] (4x4 register transpose, fused leaky).
// Smem row stride 72 bf16 -> conflict-free ldmatrix. Split-K over gridDim.y
// (chunk % 4 == 0); atomicAdd into pre-zeroed C; bias on blockIdx.y==0.
// Kb limits B's K reads; A beyond Kb must be zero-padded memory.
// ===========================================================================
#define HRS 72
#define HA_ELEM (80 * HRS)                        // 5760
#define HB_ELEM (128 * HRS)                       // 9216
#define HBUF_ELEM (2 * HA_ELEM + 2 * HB_ELEM)     // 29952 bf16
#define HS_BYTES (2 * HBUF_ELEM * 2)              // 119808 B

template<bool BNK>
__global__ void __launch_bounds__(320)
hgemm(const float* __restrict__ A, const float* __restrict__ B,
      float* __restrict__ C, const float* __restrict__ bias_n,
      const float* __restrict__ bias_m,
      int N, int K, int Kb, int lda, int ldb, int ldc, int leaky_b, int transC) {
    extern __shared__ __nv_bfloat16 hs[];
    const uint32_t sbase = smem_u32(hs);

    const int tid  = threadIdx.x;
    const int lane = tid & 31;
    const int wid  = tid >> 5;          // 0..9
    const int wm   = wid >> 1;          // 0..4 -> rows wm*16
    const int wn   = wid & 1;           // 0..1 -> cols wn*64
    const int n0   = blockIdx.x * 128;

    const int chunk = (K + gridDim.y - 1) / (int)gridDim.y;
    const int kb = min(K, (int)blockIdx.y * chunk);
    const int ke = min(K, kb + chunk);
    const int ntiles = (ke - kb + 63) >> 6;
    const int keB = min(ke, Kb);

    const uint32_t oAL = HA_ELEM;
    const uint32_t oBH = 2 * HA_ELEM, oBL = 2 * HA_ELEM + HB_ELEM;

    // ---- staging registers
    uint2 aH[4], aL[4];
    uint2 bH[7], bL[7], bH7, bL7;

    auto loadA = [&](int k0) {
        #pragma unroll
        for (int i = 0; i < 4; i++) {
            int idx = tid + i * 320;            // 80*16 = 1280 exact
            int row = idx >> 4, c4 = idx & 15;
            int gk = k0 + c4 * 4;
            float4 v = make_float4(0.f, 0.f, 0.f, 0.f);
            if (gk < ke) v = *(const float4*)(A + (size_t)row * lda + gk);
            split4(v, aH[i], aL[i]);
        }
    };
    auto storeA = [&](int buf) {
        __nv_bfloat16* base = hs + buf * HBUF_ELEM;
        #pragma unroll
        for (int i = 0; i < 4; i++) {
            int idx = tid + i * 320;
            int row = idx >> 4, c4 = idx & 15;
            uint32_t off = row * HRS + c4 * 4;
            *(uint2*)(base + off) = aH[i];
            *(uint2*)(base + oAL + off) = aL[i];
        }
    };
    auto loadB = [&](int k0) {
        if (BNK) {
            #pragma unroll
            for (int i = 0; i < 7; i++) {
                int idx = tid + i * 320;        // need 128*16 = 2048
                if (idx >= 2048) continue;
                int row = idx >> 4, c4 = idx & 15;
                int gn = n0 + row, gk = k0 + c4 * 4;
                float4 v = make_float4(0.f, 0.f, 0.f, 0.f);
                if (gk < keB && gn < N)
                    v = *(const float4*)(B + (size_t)gn * ldb + gk);
                split4(v, bH[i], bL[i]);
            }
        } else {
            // B[K,N]: groups of 4 k-rows x 4 n-cols, register transpose
            #pragma unroll
            for (int i = 0; i < 2; i++) {
                int idx = tid + i * 320;        // need 512 groups
                if (idx >= 512) continue;
                int nq = idx & 31, kq = idx >> 5;
                int gn = n0 + nq * 4, gkb = k0 + kq * 4;
                float4 r[4];
                #pragma unroll
                for (int rr = 0; rr < 4; rr++) {
                    int gk = gkb + rr;
                    float4 v = make_float4(0.f, 0.f, 0.f, 0.f);
                    if (gk < keB && gn < N)
                        v = *(const float4*)(B + (size_t)gk * ldb + gn);
                    if (leaky_b) v = leaky4(v);
                    r[rr] = v;
                }
                #pragma unroll
                for (int j = 0; j < 4; j++) {
                    float4 kv = make_float4(((float*)&r[0])[j], ((float*)&r[1])[j],
                                            ((float*)&r[2])[j], ((float*)&r[3])[j]);
                    int s = i * 4 + j;
                    if (s < 7) split4(kv, bH[s], bL[s]);
                    else       split4(kv, bH7, bL7);
                }
            }
        }
    };
    auto storeB = [&](int buf) {
        __nv_bfloat16* base = hs + buf * HBUF_ELEM;
        if (BNK) {
            #pragma unroll
            for (int i = 0; i < 7; i++) {
                int idx = tid + i * 320;
                if (idx >= 2048) continue;
                int row = idx >> 4, c4 = idx & 15;
                uint32_t off = row * HRS + c4 * 4;
                *(uint2*)(base + oBH + off) = bH[i];
                *(uint2*)(base + oBL + off) = bL[i];
            }
        } else {
            #pragma unroll
            for (int i = 0; i < 2; i++) {
                int idx = tid + i * 320;
                if (idx >= 512) continue;
                int nq = idx & 31, kq = idx >> 5;
                #pragma unroll
                for (int j = 0; j < 4; j++) {
                    int s = i * 4 + j;
                    uint32_t off = (nq * 4 + j) * HRS + kq * 4;
                    *(uint2*)(base + oBH + off) = (s < 7) ? bH[s] : bH7;
                    *(uint2*)(base + oBL + off) = (s < 7) ? bL[s] : bL7;
                }
            }
        }
    };

    float acc[8][4];
    #pragma unroll
    for (int i = 0; i < 8; i++)
        #pragma unroll
        for (int j = 0; j < 4; j++) acc[i][j] = 0.f;

    if (ntiles > 0) {
        loadA(kb); loadB(kb);
        storeA(0); storeB(0);
        __syncthreads();
    }

    const int grp = lane >> 3, lr = lane & 7;
    // ldmatrix lane-address components (constant per thread)
    const uint32_t aRow = wm * 16 + ((grp & 1) << 3) + lr;
    const uint32_t aColOff = (grp >> 1) << 3;
    const uint32_t bRowBase = wn * 64 + ((grp >> 1) << 3) + lr;
    const uint32_t bColOff = (grp & 1) << 3;

    for (int t = 0; t < ntiles; t++) {
        const int cur = t & 1;
        const bool more = (t + 1 < ntiles);
        if (more) { int k0n = kb + (t + 1) * 64; loadA(k0n); loadB(k0n); }

        const uint32_t bufb = sbase + cur * (HBUF_ELEM * 2);

        #pragma unroll 1
        for (int t3 = 0; t3 < 3; t3++) {
            // term -> A base (hi,hi,lo), B base (hi,lo,hi); arithmetic select
            const uint32_t tA = bufb + ((t3 == 2) ? oAL * 2 : 0);
            const uint32_t tB = bufb + oBH * 2 + ((t3 == 1) ? HB_ELEM * 2 : 0);

            #pragma unroll
            for (int k16 = 0; k16 < 4; k16++) {
                uint32_t a0, a1, a2, a3;
                ldsm4(a0, a1, a2, a3,
                      tA + (aRow * HRS + k16 * 16 + aColOff) * 2);
                uint32_t b[16];
                #pragma unroll
                for (int h = 0; h < 4; h++) {
                    ldsm4(b[h*4], b[h*4+1], b[h*4+2], b[h*4+3],
                          tB + ((bRowBase + h * 16) * HRS + k16 * 16 + bColOff) * 2);
                }
                #pragma unroll
                for (int nt = 0; nt < 8; nt++)
                    mma16816(acc[nt], a0, a1, a2, a3, b[nt*2], b[nt*2+1]);
            }
        }

        if (more) { storeA(cur ^ 1); storeB(cur ^ 1); }
        __syncthreads();
    }

    // ---- epilogue
    const bool first = (blockIdx.y == 0);
    const int r0 = wm * 16 + (lane >> 2);
    const int cb = n0 + wn * 64 + (lane & 3) * 2;
    #pragma unroll
    for (int nt = 0; nt < 8; nt++) {
        #pragma unroll
        for (int e = 0; e < 4; e++) {
            int gm = r0 + ((e >> 1) << 3);
            int gn = cb + nt * 8 + (e & 1);
            if (gn >= N) continue;
            float v = acc[nt][e];
            if (first) {
                if (bias_n) v += bias_n[gn];
                if (bias_m) v += bias_m[gm];
            }
            float* dst = transC ? (C + (size_t)gn * ldc + gm)
                                : (C + (size_t)gm * ldc + gn);
            atomicAdd(dst, v);
        }
    }
}

// ===========================================================================
// zero + adj in one launch: last block computes adj, the rest zero scratch+out
// ===========================================================================
__global__ void zero_adj_kernel(float* __restrict__ z, int nz,
                                float* __restrict__ o, int no,
                                const float* __restrict__ A,
                                float* __restrict__ adj) {
    if (blockIdx.x == gridDim.x - 1) {
        __shared__ float D[CC];
        int tid = threadIdx.x;
        if (tid < CC) {
            float s = 0.f;
            #pragma unroll 4
            for (int j = 0; j < CC; j++) s += A[tid * CC + j];
            D[tid] = 1.0f / sqrtf(s);
        }
        __syncthreads();
        for (int idx = tid; idx < CC * CC; idx += blockDim.x) {
            int i = idx / CC, j = idx % CC;
            adj[idx] = D[i] * A[j * CC + i] * D[j];
        }
        return;
    }
    int i = blockIdx.x * blockDim.x + threadIdx.x;
    if (i < nz) z[i] = 0.f;
    else if (i - nz < no) o[i - nz] = 0.f;
}

__global__ void dot_bias_kernel(const float* __restrict__ cls,
                                const float* __restrict__ b,
                                float* __restrict__ t, int J) {
    int c = blockIdx.x;
    float s = 0.f;
    for (int j = threadIdx.x; j < J; j += blockDim.x)
        s += cls[c * J + j] * b[j];
    #pragma unroll
    for (int o = 16; o > 0; o >>= 1) s += __shfl_down_sync(0xFFFFFFFFu, s, o);
    __shared__ float red[8];
    if ((threadIdx.x & 31) == 0) red[threadIdx.x >> 5] = s;
    __syncthreads();
    if (threadIdx.x == 0) {
        float tot = 0.f;
        #pragma unroll
        for (int w = 0; w < 8; w++) tot += red[w];
        t[c] = tot;
    }
}

// ===========================================================================
extern "C" void kernel_launch(void* const* d_in, const int* in_sizes, int n_in,
                              void* d_out, int out_size) {
    const float* feature = (const float*)d_in[0];   // [1024, 2048]
    const float* inp     = (const float*)d_in[1];   // [1, 80, 300]
    const float* A       = (const float*)d_in[2];   // [80, 80]
    const float* Wgc1    = (const float*)d_in[3];   // [300, 1024]
    const float* Wgc2    = (const float*)d_in[4];   // [1024, 2048]
    const float* Wimg    = (const float*)d_in[5];   // [8000, 2048]
    const float* bimg    = (const float*)d_in[6];   // [8000]
    const float* Wcls    = (const float*)d_in[7];   // [8000, 2048]
    const float* bcls    = (const float*)d_in[8];   // [8000]
    float* out = (float*)d_out;                     // [1024, 80] row-major

    float* buf;
    cudaGetSymbolAddress((void**)&buf, g_buf);
    float* adj = buf + OFF_ADJ;
    float* t   = buf + OFF_T;
    float* P   = buf + OFF_P;
    float* Q   = buf + OFF_Q;
    float* x1  = buf + OFF_X1;
    float* x2  = buf + OFF_X2;
    float* cls = buf + OFF_CLS;
    float* Mm  = buf + OFF_M;

    cudaFuncSetAttribute(hgemm<false>,
                         cudaFuncAttributeMaxDynamicSharedMemorySize, HS_BYTES);
    cudaFuncSetAttribute(hgemm<true>,
                         cudaFuncAttributeMaxDynamicSharedMemorySize, HS_BYTES);

    // Zero all hgemm targets (P..M contiguous) + out, plus adj, one launch.
    {
        int ntot = SZ_ZERO + BB * CC;
        int nblk = (ntot + 255) / 256 + 1;   // +1: adj block
        zero_adj_kernel<<<nblk, 256>>>(P, SZ_ZERO, out, BB * CC, A, adj);
    }

    // P = adj @ inp0                 [80,300]  K=80, split 4 (chunk 20)
    hgemm<false><<<dim3(3, 4), 320, HS_BYTES>>>(
        adj, inp, P, nullptr, nullptr, DW, CC, CC, CC, DW, DWP, 0, 0);

    // x1 = P @ W_gc1                 [80,1024] K=304 pad (Kb=300), split 4 (chunk 76)
    hgemm<false><<<dim3(8, 4), 320, HS_BYTES>>>(
        P, Wgc1, x1, nullptr, nullptr, 1024, DWP, DW, DWP, 1024, 1024, 0, 0);

    // Q = adj @ leaky(x1)            [80,1024] K=80, split 4 (chunk 20)
    hgemm<false><<<dim3(8, 4), 320, HS_BYTES>>>(
        adj, x1, Q, nullptr, nullptr, 1024, CC, CC, CC, 1024, 1024, 1, 0);

    // x2 = Q @ W_gc2                 [80,2048] K=1024, split 8 (chunk 128)
    hgemm<false><<<dim3(16, 8), 320, HS_BYTES>>>(
        Q, Wgc2, x2, nullptr, nullptr, 2048, 1024, 1024, 1024, 2048, 2048, 0, 0);

    // cls = x2 @ W_cls^T + b_cls     [80,8000] K=2048, split 2 (chunk 1024)
    hgemm<true><<<dim3(63, 2), 320, HS_BYTES>>>(
        x2, Wcls, cls, bcls, nullptr, JJ, 2048, 2048, 2048, 2048, JJ, 0, 0);

    // t = cls @ b_img                [80]
    dot_bias_kernel<<<CC, 256>>>(cls, bimg, t, JJ);

    // M = cls @ W_img                [80,2048] K=8000, split 8 (chunk 1000)
    hgemm<false><<<dim3(16, 8), 320, HS_BYTES>>>(
        cls, Wimg, Mm, nullptr, nullptr, 2048, JJ, JJ, JJ, 2048, 2048, 0, 0);

    // out^T: C[c,b] = Mm[c,:].feature[b,:] + t[c] -> out[b*80+c]
    //                                [80,1024] K=2048, split 16 (chunk 128)
    hgemm<true><<<dim3(8, 16), 320, HS_BYTES>>>(
        Mm, feature, out, nullptr, t, BB, 2048, 2048, 2048, 2048, CC, 0, 1);
}

// round 14
// speedup vs baseline: 2.3829x; 1.1615x over previous
#include <cuda_runtime.h>
#include <cuda_bf16.h>
#include <cstdint>

// Problem dims
#define BB 1024
#define CC 80
#define DW 300
#define DWP 304          // padded DW for aligned float4 rows
#define JJ 8000
#define ICH 2048

// ---- scratch layout in one device global (no allocations allowed) ----------
// Non-zeroed: adj, t. Zeroed contiguous (all hgemm atomic targets): P..M
#define OFF_ADJ 0
#define SZ_ADJ  (CC*CC)
#define OFF_T   (OFF_ADJ + SZ_ADJ)
#define SZ_T    (CC)
#define OFF_P   (OFF_T + SZ_T)
#define SZ_P    (CC*DWP)
#define OFF_Q   (OFF_P + SZ_P)
#define SZ_Q    (CC*1024)
#define OFF_X1  (OFF_Q + SZ_Q)
#define SZ_X1   (CC*1024)
#define OFF_X2  (OFF_X1 + SZ_X1)
#define SZ_X2   (CC*2048)
#define OFF_CLS (OFF_X2 + SZ_X2)
#define SZ_CLS  (CC*JJ)
#define OFF_M   (OFF_CLS + SZ_CLS)
#define SZ_M    (CC*2048)
#define SZ_ZERO (SZ_P + SZ_Q + SZ_X1 + SZ_X2 + SZ_CLS + SZ_M)
#define SZ_TOT  (OFF_M + SZ_M)

__device__ float g_buf[SZ_TOT];

// ===========================================================================
// helpers
// ===========================================================================
__device__ __forceinline__ uint32_t smem_u32(const void* p) {
    uint32_t a;
    asm("{ .reg .u64 t; cvta.to.shared.u64 t, %1; cvt.u32.u64 %0, t; }"
        : "=r"(a) : "l"(p));
    return a;
}
__device__ __forceinline__ void ldsm4(uint32_t& r0, uint32_t& r1,
                                      uint32_t& r2, uint32_t& r3, uint32_t addr) {
    asm volatile("ldmatrix.sync.aligned.m8n8.x4.shared.b16 {%0,%1,%2,%3}, [%4];"
                 : "=r"(r0), "=r"(r1), "=r"(r2), "=r"(r3) : "r"(addr));
}
__device__ __forceinline__ void mma16816(float* c,
        uint32_t a0, uint32_t a1, uint32_t a2, uint32_t a3,
        uint32_t b0, uint32_t b1) {
    asm volatile("mma.sync.aligned.m16n8k16.row.col.f32.bf16.bf16.f32 "
                 "{%0,%1,%2,%3}, {%4,%5,%6,%7}, {%8,%9}, {%0,%1,%2,%3};"
                 : "+f"(c[0]), "+f"(c[1]), "+f"(c[2]), "+f"(c[3])
                 : "r"(a0), "r"(a1), "r"(a2), "r"(a3), "r"(b0), "r"(b1));
}
// fp32x4 -> packed bf16 hi pair-quad + lo pair-quad, via bf16x2 cvt.
// hi.x packs {lo16(v.x), hi16(v.y)} matching __halves2bfloat162(x, y).
__device__ __forceinline__ void split4(float4 v, uint2& hi, uint2& lo) {
    uint32_t h01, h23;
    asm("cvt.rn.bf16x2.f32 %0, %1, %2;" : "=r"(h01) : "f"(v.y), "f"(v.x));
    asm("cvt.rn.bf16x2.f32 %0, %1, %2;" : "=r"(h23) : "f"(v.w), "f"(v.z));
    float h0 = __uint_as_float(h01 << 16);
    float h1 = __uint_as_float(h01 & 0xFFFF0000u);
    float h2 = __uint_as_float(h23 << 16);
    float h3 = __uint_as_float(h23 & 0xFFFF0000u);
    uint32_t l01, l23;
    asm("cvt.rn.bf16x2.f32 %0, %1, %2;" : "=r"(l01) : "f"(v.y - h1), "f"(v.x - h0));
    asm("cvt.rn.bf16x2.f32 %0, %1, %2;" : "=r"(l23) : "f"(v.w - h3), "f"(v.z - h2));
    hi.x = h01; hi.y = h23; lo.x = l01; lo.y = l23;
}
__device__ __forceinline__ float4 leaky4(float4 v) {
    v.x = v.x > 0.f ? v.x : 0.2f * v.x;
    v.y = v.y > 0.f ? v.y : 0.2f * v.y;
    v.z = v.z > 0.f ? v.z : 0.2f * v.z;
    v.w = v.w > 0.f ? v.w : 0.2f * v.w;
    return v;
}

// ===========================================================================
// Tensor-core GEMM via mma.sync (HMMA; baseline PTX, safe at compute_103):
//   C[80, N] += A[80, K] * op(B), split bf16 (hi/lo, 3 terms), fp32 accum.
// Tile 80 x 128, k-tile 32 fp32 (smem 65KB double-buffered -> 2 CTA/SM).
// 320 threads = 10 warps (5m x 2n); each warp m16 x n64 -> 8 acc chains.
// 3-term loop NOT unrolled (small I$ body). BNK=true: B is [N,K]; false:
// [K,N] (4x4 register transpose, fused leaky). Smem row stride 40 bf16
// (80B) -> conflict-free ldmatrix. Split-K over gridDim.y (chunk % 4 == 0);
// atomicAdd into pre-zeroed C; bias on blockIdx.y==0. Kb limits B's K reads.
// ===========================================================================
#define HRS 40
#define HA_ELEM (80 * HRS)                        // 3200
#define HB_ELEM (128 * HRS)                       // 5120
#define HBUF_ELEM (2 * HA_ELEM + 2 * HB_ELEM)     // 16640 bf16
#define HS_BYTES (2 * HBUF_ELEM * 2)              // 66560 B

template<bool BNK>
__global__ void __launch_bounds__(320, 2)
hgemm(const float* __restrict__ A, const float* __restrict__ B,
      float* __restrict__ C, const float* __restrict__ bias_n,
      const float* __restrict__ bias_m,
      int N, int K, int Kb, int lda, int ldb, int ldc, int leaky_b, int transC) {
    extern __shared__ __nv_bfloat16 hs[];
    const uint32_t sbase = smem_u32(hs);

    const int tid  = threadIdx.x;
    const int lane = tid & 31;
    const int wid  = tid >> 5;          // 0..9
    const int wm   = wid >> 1;          // 0..4 -> rows wm*16
    const int wn   = wid & 1;           // 0..1 -> cols wn*64
    const int n0   = blockIdx.x * 128;

    const int chunk = (K + gridDim.y - 1) / (int)gridDim.y;
    const int kb = min(K, (int)blockIdx.y * chunk);
    const int ke = min(K, kb + chunk);
    const int ntiles = (ke - kb + 31) >> 5;
    const int keB = min(ke, Kb);

    const uint32_t oAL = HA_ELEM;
    const uint32_t oBH = 2 * HA_ELEM, oBL = 2 * HA_ELEM + HB_ELEM;

    // ---- staging registers (k-tile 32)
    uint2 aH[2], aL[2];
    uint2 bH[4], bL[4];

    auto loadA = [&](int k0) {
        #pragma unroll
        for (int i = 0; i < 2; i++) {
            int idx = tid + i * 320;            // 80 rows x 8 float4 = 640
            int row = idx >> 3, c4 = idx & 7;
            int gk = k0 + c4 * 4;
            float4 v = make_float4(0.f, 0.f, 0.f, 0.f);
            if (gk < ke) v = *(const float4*)(A + (size_t)row * lda + gk);
            split4(v, aH[i], aL[i]);
        }
    };
    auto storeA = [&](int buf) {
        __nv_bfloat16* base = hs + buf * HBUF_ELEM;
        #pragma unroll
        for (int i = 0; i < 2; i++) {
            int idx = tid + i * 320;
            int row = idx >> 3, c4 = idx & 7;
            uint32_t off = row * HRS + c4 * 4;
            *(uint2*)(base + off) = aH[i];
            *(uint2*)(base + oAL + off) = aL[i];
        }
    };
    auto loadB = [&](int k0) {
        if (BNK) {
            #pragma unroll
            for (int i = 0; i < 4; i++) {
                int idx = tid + i * 320;        // 128 rows x 8 float4 = 1024
                if (idx >= 1024) continue;
                int row = idx >> 3, c4 = idx & 7;
                int gn = n0 + row, gk = k0 + c4 * 4;
                float4 v = make_float4(0.f, 0.f, 0.f, 0.f);
                if (gk < keB && gn < N)
                    v = *(const float4*)(B + (size_t)gn * ldb + gk);
                split4(v, bH[i], bL[i]);
            }
        } else {
            // B[K,N]: groups of 4 k-rows x 4 n-cols; 8 kq x 32 nq = 256 groups
            if (tid < 256) {
                int nq = tid & 31, kq = tid >> 5;
                int gn = n0 + nq * 4, gkb = k0 + kq * 4;
                float4 r[4];
                #pragma unroll
                for (int rr = 0; rr < 4; rr++) {
                    int gk = gkb + rr;
                    float4 v = make_float4(0.f, 0.f, 0.f, 0.f);
                    if (gk < keB && gn < N)
                        v = *(const float4*)(B + (size_t)gk * ldb + gn);
                    if (leaky_b) v = leaky4(v);
                    r[rr] = v;
                }
                #pragma unroll
                for (int j = 0; j < 4; j++) {
                    float4 kv = make_float4(((float*)&r[0])[j], ((float*)&r[1])[j],
                                            ((float*)&r[2])[j], ((float*)&r[3])[j]);
                    split4(kv, bH[j], bL[j]);
                }
            }
        }
    };
    auto storeB = [&](int buf) {
        __nv_bfloat16* base = hs + buf * HBUF_ELEM;
        if (BNK) {
            #pragma unroll
            for (int i = 0; i < 4; i++) {
                int idx = tid + i * 320;
                if (idx >= 1024) continue;
                int row = idx >> 3, c4 = idx & 7;
                uint32_t off = row * HRS + c4 * 4;
                *(uint2*)(base + oBH + off) = bH[i];
                *(uint2*)(base + oBL + off) = bL[i];
            }
        } else {
            if (tid < 256) {
                int nq = tid & 31, kq = tid >> 5;
                #pragma unroll
                for (int j = 0; j < 4; j++) {
                    uint32_t off = (nq * 4 + j) * HRS + kq * 4;
                    *(uint2*)(base + oBH + off) = bH[j];
                    *(uint2*)(base + oBL + off) = bL[j];
                }
            }
        }
    };

    float acc[8][4];
    #pragma unroll
    for (int i = 0; i < 8; i++)
        #pragma unroll
        for (int j = 0; j < 4; j++) acc[i][j] = 0.f;

    if (ntiles > 0) {
        loadA(kb); loadB(kb);
        storeA(0); storeB(0);
        __syncthreads();
    }

    const int grp = lane >> 3, lr = lane & 7;
    const uint32_t aRow = wm * 16 + ((grp & 1) << 3) + lr;
    const uint32_t aColOff = (grp >> 1) << 3;
    const uint32_t bRowBase = wn * 64 + ((grp >> 1) << 3) + lr;
    const uint32_t bColOff = (grp & 1) << 3;

    for (int t = 0; t < ntiles; t++) {
        const int cur = t & 1;
        const bool more = (t + 1 < ntiles);
        if (more) { int k0n = kb + (t + 1) * 32; loadA(k0n); loadB(k0n); }

        const uint32_t bufb = sbase + cur * (HBUF_ELEM * 2);

        #pragma unroll 1
        for (int t3 = 0; t3 < 3; t3++) {
            // term -> A base (hi,hi,lo), B base (hi,lo,hi)
            const uint32_t tA = bufb + ((t3 == 2) ? oAL * 2 : 0);
            const uint32_t tB = bufb + oBH * 2 + ((t3 == 1) ? HB_ELEM * 2 : 0);

            #pragma unroll
            for (int k16 = 0; k16 < 2; k16++) {
                uint32_t a0, a1, a2, a3;
                ldsm4(a0, a1, a2, a3,
                      tA + (aRow * HRS + k16 * 16 + aColOff) * 2);
                uint32_t b[16];
                #pragma unroll
                for (int h = 0; h < 4; h++) {
                    ldsm4(b[h*4], b[h*4+1], b[h*4+2], b[h*4+3],
                          tB + ((bRowBase + h * 16) * HRS + k16 * 16 + bColOff) * 2);
                }
                #pragma unroll
                for (int nt = 0; nt < 8; nt++)
                    mma16816(acc[nt], a0, a1, a2, a3, b[nt*2], b[nt*2+1]);
            }
        }

        if (more) { storeA(cur ^ 1); storeB(cur ^ 1); }
        __syncthreads();
    }

    // ---- epilogue
    const bool first = (blockIdx.y == 0);
    const int r0 = wm * 16 + (lane >> 2);
    const int cb = n0 + wn * 64 + (lane & 3) * 2;
    #pragma unroll
    for (int nt = 0; nt < 8; nt++) {
        #pragma unroll
        for (int e = 0; e < 4; e++) {
            int gm = r0 + ((e >> 1) << 3);
            int gn = cb + nt * 8 + (e & 1);
            if (gn >= N) continue;
            float v = acc[nt][e];
            if (first) {
                if (bias_n) v += bias_n[gn];
                if (bias_m) v += bias_m[gm];
            }
            float* dst = transC ? (C + (size_t)gn * ldc + gm)
                                : (C + (size_t)gm * ldc + gn);
            atomicAdd(dst, v);
        }
    }
}

// ===========================================================================
// zero + adj in one launch: last block computes adj, the rest zero scratch+out
// ===========================================================================
__global__ void zero_adj_kernel(float* __restrict__ z, int nz,
                                float* __restrict__ o, int no,
                                const float* __restrict__ A,
                                float* __restrict__ adj) {
    if (blockIdx.x == gridDim.x - 1) {
        __shared__ float D[CC];
        int tid = threadIdx.x;
        if (tid < CC) {
            float s = 0.f;
            #pragma unroll 4
            for (int j = 0; j < CC; j++) s += A[tid * CC + j];
            D[tid] = 1.0f / sqrtf(s);
        }
        __syncthreads();
        for (int idx = tid; idx < CC * CC; idx += blockDim.x) {
            int i = idx / CC, j = idx % CC;
            adj[idx] = D[i] * A[j * CC + i] * D[j];
        }
        return;
    }
    int i = blockIdx.x * blockDim.x + threadIdx.x;
    if (i < nz) z[i] = 0.f;
    else if (i - nz < no) o[i - nz] = 0.f;
}

__global__ void dot_bias_kernel(const float* __restrict__ cls,
                                const float* __restrict__ b,
                                float* __restrict__ t, int J) {
    int c = blockIdx.x;
    float s = 0.f;
    for (int j = threadIdx.x; j < J; j += blockDim.x)
        s += cls[c * J + j] * b[j];
    #pragma unroll
    for (int o = 16; o > 0; o >>= 1) s += __shfl_down_sync(0xFFFFFFFFu, s, o);
    __shared__ float red[8];
    if ((threadIdx.x & 31) == 0) red[threadIdx.x >> 5] = s;
    __syncthreads();
    if (threadIdx.x == 0) {
        float tot = 0.f;
        #pragma unroll
        for (int w = 0; w < 8; w++) tot += red[w];
        t[c] = tot;
    }
}

// ===========================================================================
extern "C" void kernel_launch(void* const* d_in, const int* in_sizes, int n_in,
                              void* d_out, int out_size) {
    const float* feature = (const float*)d_in[0];   // [1024, 2048]
    const float* inp     = (const float*)d_in[1];   // [1, 80, 300]
    const float* A       = (const float*)d_in[2];   // [80, 80]
    const float* Wgc1    = (const float*)d_in[3];   // [300, 1024]
    const float* Wgc2    = (const float*)d_in[4];   // [1024, 2048]
    const float* Wimg    = (const float*)d_in[5];   // [8000, 2048]
    const float* bimg    = (const float*)d_in[6];   // [8000]
    const float* Wcls    = (const float*)d_in[7];   // [8000, 2048]
    const float* bcls    = (const float*)d_in[8];   // [8000]
    float* out = (float*)d_out;                     // [1024, 80] row-major

    float* buf;
    cudaGetSymbolAddress((void**)&buf, g_buf);
    float* adj = buf + OFF_ADJ;
    float* t   = buf + OFF_T;
    float* P   = buf + OFF_P;
    float* Q   = buf + OFF_Q;
    float* x1  = buf + OFF_X1;
    float* x2  = buf + OFF_X2;
    float* cls = buf + OFF_CLS;
    float* Mm  = buf + OFF_M;

    cudaFuncSetAttribute(hgemm<false>,
                         cudaFuncAttributeMaxDynamicSharedMemorySize, HS_BYTES);
    cudaFuncSetAttribute(hgemm<true>,
                         cudaFuncAttributeMaxDynamicSharedMemorySize, HS_BYTES);

    // Zero all hgemm targets (P..M contiguous) + out, plus adj, one launch.
    {
        int ntot = SZ_ZERO + BB * CC;
        int nblk = (ntot + 255) / 256 + 1;   // +1: adj block
        zero_adj_kernel<<<nblk, 256>>>(P, SZ_ZERO, out, BB * CC, A, adj);
    }

    // P = adj @ inp0                 [80,300]  K=80, split 4 (chunk 20)
    hgemm<false><<<dim3(3, 4), 320, HS_BYTES>>>(
        adj, inp, P, nullptr, nullptr, DW, CC, CC, CC, DW, DWP, 0, 0);

    // x1 = P @ W_gc1                 [80,1024] K=304 pad (Kb=300), split 4 (chunk 76)
    hgemm<false><<<dim3(8, 4), 320, HS_BYTES>>>(
        P, Wgc1, x1, nullptr, nullptr, 1024, DWP, DW, DWP, 1024, 1024, 0, 0);

    // Q = adj @ leaky(x1)            [80,1024] K=80, split 4 (chunk 20)
    hgemm<false><<<dim3(8, 4), 320, HS_BYTES>>>(
        adj, x1, Q, nullptr, nullptr, 1024, CC, CC, CC, 1024, 1024, 1, 0);

    // x2 = Q @ W_gc2                 [80,2048] K=1024, split 16 (chunk 64, 256 blk)
    hgemm<false><<<dim3(16, 16), 320, HS_BYTES>>>(
        Q, Wgc2, x2, nullptr, nullptr, 2048, 1024, 1024, 1024, 2048, 2048, 0, 0);

    // cls = x2 @ W_cls^T + b_cls     [80,8000] K=2048, split 4 (chunk 512, 252 blk)
    hgemm<true><<<dim3(63, 4), 320, HS_BYTES>>>(
        x2, Wcls, cls, bcls, nullptr, JJ, 2048, 2048, 2048, 2048, JJ, 0, 0);

    // t = cls @ b_img                [80]
    dot_bias_kernel<<<CC, 256>>>(cls, bimg, t, JJ);

    // M = cls @ W_img                [80,2048] K=8000, split 16 (chunk 500, 256 blk)
    hgemm<false><<<dim3(16, 16), 320, HS_BYTES>>>(
        cls, Wimg, Mm, nullptr, nullptr, 2048, JJ, JJ, JJ, 2048, 2048, 0, 0);

    // out^T: C[c,b] = Mm[c,:].feature[b,:] + t[c] -> out[b*80+c]
    //                                [80,1024] K=2048, split 32 (chunk 64, 256 blk)
    hgemm<true><<<dim3(8, 32), 320, HS_BYTES>>>(
        Mm, feature, out, nullptr, t, BB, 2048, 2048, 2048, 2048, CC, 0, 1);
}